// round 1
// baseline (speedup 1.0000x reference)
#include <cuda_runtime.h>

#define NN 50000
#define EE 800000
#define BCAP 128   // per-node bucket capacity (true max in-degree ~40 for this data)

// ---------------- scratch (static device globals; no allocation) ----------------
__device__ int   g_cnt[NN];
__device__ int   g_bucket[(size_t)NN * BCAP];
__device__ float g_dinv[NN];
__device__ float g_h1 [(size_t)NN * 64];
__device__ float g_h2 [(size_t)NN * 64];
__device__ float g_y  [(size_t)NN * 64];
__device__ float g_S  [(size_t)NN * 64];
__device__ float g_cat[(size_t)NN * 192];
__device__ float g_c1 [(size_t)NN * 64];
__device__ float g_c2 [(size_t)NN * 64];
__device__ float g_h3 [(size_t)NN * 64];

// ---------------- graph structure build ----------------
__global__ void zero_cnt_kernel() {
    int i = blockIdx.x * 256 + threadIdx.x;
    if (i < NN) g_cnt[i] = 0;
}

__global__ void build_bucket_kernel(const int* __restrict__ src,
                                    const int* __restrict__ dst) {
    int e = blockIdx.x * 256 + threadIdx.x;
    if (e >= EE) return;
    int d = dst[e];
    int p = atomicAdd(&g_cnt[d], 1);
    if (p < BCAP) g_bucket[(size_t)d * BCAP + p] = src[e];
}

__global__ void dinv_kernel() {
    int i = blockIdx.x * 256 + threadIdx.x;
    if (i >= NN) return;
    int c = g_cnt[i];
    float d = (float)(c > 0 ? c : 1);
    g_dinv[i] = rsqrtf(d);
}

// ---------------- dense GEMM: out[N,64] = relu?(X[N,KD] @ W[64,KD]^T + b) ----------------
// Block: 256 threads = 4 row-groups x 64 cols; each thread owns 4 rows (reg-blocked).
// W staged to SMEM transposed -> conflict-free LDS; X rows broadcast via L1 (same addr per warp).
template <int KD>
__global__ void __launch_bounds__(256) gemm64_kernel(const float* __restrict__ X,
                                                     const float* __restrict__ W,
                                                     const float* __restrict__ bias,
                                                     float* __restrict__ out,
                                                     int do_relu) {
    __shared__ float Wsh[KD * 64];
    int tid = threadIdx.x;
    for (int idx = tid; idx < KD * 64; idx += 256) {
        int k = idx >> 6, c = idx & 63;
        Wsh[idx] = W[c * KD + k];
    }
    __syncthreads();

    int c  = tid & 63;
    int rg = tid >> 6;                         // 0..3
    size_t row0 = (size_t)blockIdx.x * 16 + rg * 4;
    const float* Xb = X + row0 * KD;
    float bv = bias[c];
    float a0 = 0.f, a1 = 0.f, a2 = 0.f, a3 = 0.f;

#pragma unroll 8
    for (int k = 0; k < KD; k += 4) {
        float w0 = Wsh[(k + 0) * 64 + c];
        float w1 = Wsh[(k + 1) * 64 + c];
        float w2 = Wsh[(k + 2) * 64 + c];
        float w3 = Wsh[(k + 3) * 64 + c];
        float4 x0 = *(const float4*)(Xb + 0 * KD + k);
        float4 x1 = *(const float4*)(Xb + 1 * KD + k);
        float4 x2 = *(const float4*)(Xb + 2 * KD + k);
        float4 x3 = *(const float4*)(Xb + 3 * KD + k);
        a0 = fmaf(x0.x, w0, fmaf(x0.y, w1, fmaf(x0.z, w2, fmaf(x0.w, w3, a0))));
        a1 = fmaf(x1.x, w0, fmaf(x1.y, w1, fmaf(x1.z, w2, fmaf(x1.w, w3, a1))));
        a2 = fmaf(x2.x, w0, fmaf(x2.y, w1, fmaf(x2.z, w2, fmaf(x2.w, w3, a2))));
        a3 = fmaf(x3.x, w0, fmaf(x3.y, w1, fmaf(x3.z, w2, fmaf(x3.w, w3, a3))));
    }

    float v0 = a0 + bv, v1 = a1 + bv, v2 = a2 + bv, v3 = a3 + bv;
    if (do_relu) {
        v0 = fmaxf(v0, 0.f); v1 = fmaxf(v1, 0.f);
        v2 = fmaxf(v2, 0.f); v3 = fmaxf(v3, 0.f);
    }
    float* ob = out + row0 * 64 + c;
    ob[0 * 64] = v0; ob[1 * 64] = v1; ob[2 * 64] = v2; ob[3 * 64] = v3;
}

// ---------------- SpMM gather: S[n,:] = sum_{e: dst=n} y[src[e],:] ----------------
// Warp per node, float2 per lane (64 feats). No atomics; single coalesced store.
__global__ void __launch_bounds__(256) spmm_kernel() {
    int n = (blockIdx.x * 256 + threadIdx.x) >> 5;
    if (n >= NN) return;
    int lane = threadIdx.x & 31;
    int cnt = g_cnt[n];
    if (cnt > BCAP) cnt = BCAP;
    const int* bk = &g_bucket[(size_t)n * BCAP];
    const float* yb = g_y + (size_t)lane * 2;
    float2 acc  = make_float2(0.f, 0.f);
    float2 acc2 = make_float2(0.f, 0.f);
    int i = 0;
    for (; i + 1 < cnt; i += 2) {
        int s0 = bk[i], s1 = bk[i + 1];
        float2 v0 = *(const float2*)(yb + (size_t)s0 * 64);
        float2 v1 = *(const float2*)(yb + (size_t)s1 * 64);
        acc.x  += v0.x; acc.y  += v0.y;
        acc2.x += v1.x; acc2.y += v1.y;
    }
    if (i < cnt) {
        int s = bk[i];
        float2 v = *(const float2*)(yb + (size_t)s * 64);
        acc.x += v.x; acc.y += v.y;
    }
    acc.x += acc2.x; acc.y += acc2.y;
    *(float2*)(g_S + (size_t)n * 64 + lane * 2) = acc;
}

// ---------------- Chebyshev elementwise glue (re_norm == 1 simplification) ----------------
// prep: y = h * dinv ; cat[:,0:64] = h
__global__ void cheb_prep_kernel(const float* __restrict__ h) {
    int i = blockIdx.x * 256 + threadIdx.x;       // i < NN*16 (float4 units)
    int row = i >> 4, c4 = i & 15;
    float dv = g_dinv[row];
    float4 hv = ((const float4*)h)[i];
    float4 yv = make_float4(hv.x * dv, hv.y * dv, hv.z * dv, hv.w * dv);
    ((float4*)g_y)[i] = yv;
    ((float4*)g_cat)[(size_t)row * 48 + c4] = hv;
}

// mid: t1 = S*dinv ; cat[:,64:128] = -t1 ; y = t1*dinv
__global__ void cheb_mid_kernel() {
    int i = blockIdx.x * 256 + threadIdx.x;
    int row = i >> 4, c4 = i & 15;
    float dv = g_dinv[row];
    float4 sv = ((const float4*)g_S)[i];
    float4 t = make_float4(sv.x * dv, sv.y * dv, sv.z * dv, sv.w * dv);
    ((float4*)g_cat)[(size_t)row * 48 + 16 + c4] = make_float4(-t.x, -t.y, -t.z, -t.w);
    ((float4*)g_y)[i] = make_float4(t.x * dv, t.y * dv, t.z * dv, t.w * dv);
}

// post: cat[:,128:192] = 2*S*dinv - h
__global__ void cheb_post_kernel(const float* __restrict__ h) {
    int i = blockIdx.x * 256 + threadIdx.x;
    int row = i >> 4, c4 = i & 15;
    float dv2 = 2.f * g_dinv[row];
    float4 sv = ((const float4*)g_S)[i];
    float4 hv = ((const float4*)h)[i];
    ((float4*)g_cat)[(size_t)row * 48 + 32 + c4] =
        make_float4(fmaf(sv.x, dv2, -hv.x), fmaf(sv.y, dv2, -hv.y),
                    fmaf(sv.z, dv2, -hv.z), fmaf(sv.w, dv2, -hv.w));
}

// ---------------- final head: out[N,2] = X[N,64] @ W4[2,64]^T + b4 ----------------
__global__ void __launch_bounds__(256) gemm_out_kernel(const float* __restrict__ X,
                                                       const float* __restrict__ W,
                                                       const float* __restrict__ b,
                                                       float* __restrict__ out) {
    __shared__ float Wsh[128];
    __shared__ float bsh[2];
    if (threadIdx.x < 128) Wsh[threadIdx.x] = W[threadIdx.x];
    if (threadIdx.x < 2)   bsh[threadIdx.x] = b[threadIdx.x];
    __syncthreads();
    int r = blockIdx.x * 256 + threadIdx.x;
    if (r >= NN) return;
    float a0 = bsh[0], a1 = bsh[1];
    const float* xr = X + (size_t)r * 64;
#pragma unroll
    for (int k = 0; k < 64; k += 4) {
        float4 xv = *(const float4*)(xr + k);
        a0 = fmaf(xv.x, Wsh[k], fmaf(xv.y, Wsh[k + 1], fmaf(xv.z, Wsh[k + 2], fmaf(xv.w, Wsh[k + 3], a0))));
        a1 = fmaf(xv.x, Wsh[64 + k], fmaf(xv.y, Wsh[64 + k + 1], fmaf(xv.z, Wsh[64 + k + 2], fmaf(xv.w, Wsh[64 + k + 3], a1))));
    }
    out[(size_t)r * 2 + 0] = a0;
    out[(size_t)r * 2 + 1] = a1;
}

// ---------------- launch ----------------
extern "C" void kernel_launch(void* const* d_in, const int* in_sizes, int n_in,
                              void* d_out, int out_size) {
    const float* in_feat = (const float*)d_in[0];
    const int*   src     = (const int*)d_in[1];
    const int*   dst     = (const int*)d_in[2];
    const float* W1  = (const float*)d_in[3];
    const float* b1  = (const float*)d_in[4];
    const float* W2  = (const float*)d_in[5];
    const float* b2  = (const float*)d_in[6];
    const float* Wc1 = (const float*)d_in[7];
    const float* bc1 = (const float*)d_in[8];
    const float* Wc2 = (const float*)d_in[9];
    const float* bc2 = (const float*)d_in[10];
    const float* W3  = (const float*)d_in[11];
    const float* b3  = (const float*)d_in[12];
    const float* W4  = (const float*)d_in[13];
    const float* b4  = (const float*)d_in[14];
    float* out = (float*)d_out;

    float *h1, *h2, *cat, *c1, *c2, *h3;
    cudaGetSymbolAddress((void**)&h1,  g_h1);
    cudaGetSymbolAddress((void**)&h2,  g_h2);
    cudaGetSymbolAddress((void**)&cat, g_cat);
    cudaGetSymbolAddress((void**)&c1,  g_c1);
    cudaGetSymbolAddress((void**)&c2,  g_c2);
    cudaGetSymbolAddress((void**)&h3,  g_h3);

    const int GN  = (NN + 255) / 256;   // 196 blocks for node-parallel
    const int GE  = EE / 256;           // 3125 blocks, exact
    const int GR  = NN / 16;            // 3125 blocks for gemm64 (50000 = 16*3125)
    const int GV  = (NN * 16) / 256;    // 3125 blocks, float4 elementwise
    const int GW  = (NN * 32 + 255) / 256; // warp-per-node spmm: 6250 blocks

    // graph structure
    zero_cnt_kernel<<<GN, 256>>>();
    build_bucket_kernel<<<GE, 256>>>(src, dst);
    dinv_kernel<<<GN, 256>>>();

    // MLP front
    gemm64_kernel<128><<<GR, 256>>>(in_feat, W1, b1, h1, 1);
    gemm64_kernel<64><<<GR, 256>>>(h1, W2, b2, h2, 1);

    // ChebConv 1 (h2 -> c1)
    cheb_prep_kernel<<<GV, 256>>>(h2);
    spmm_kernel<<<GW, 256>>>();
    cheb_mid_kernel<<<GV, 256>>>();
    spmm_kernel<<<GW, 256>>>();
    cheb_post_kernel<<<GV, 256>>>(h2);
    gemm64_kernel<192><<<GR, 256>>>(cat, Wc1, bc1, c1, 1);

    // ChebConv 2 (c1 -> c2)
    cheb_prep_kernel<<<GV, 256>>>(c1);
    spmm_kernel<<<GW, 256>>>();
    cheb_mid_kernel<<<GV, 256>>>();
    spmm_kernel<<<GW, 256>>>();
    cheb_post_kernel<<<GV, 256>>>(c1);
    gemm64_kernel<192><<<GR, 256>>>(cat, Wc2, bc2, c2, 1);

    // MLP back + head
    gemm64_kernel<64><<<GR, 256>>>(c2, W3, b3, h3, 1);
    gemm_out_kernel<<<GN, 256>>>(h3, W4, b4, out);
}

// round 2
// speedup vs baseline: 3.4211x; 3.4211x over previous
#include <cuda_runtime.h>

#define NN 50000
#define EE 800000
#define BCAP 128   // per-node bucket capacity (true max in-degree ~40 for this data)

// ---------------- scratch (static device globals; no allocation) ----------------
__device__ int   g_cnt[NN];
__device__ int   g_bucket[(size_t)NN * BCAP];
__device__ float g_dinv[NN];
__device__ float g_h1 [(size_t)NN * 64];
__device__ float g_h2 [(size_t)NN * 64];
__device__ float g_y  [(size_t)NN * 64];
__device__ float g_S  [(size_t)NN * 64];
__device__ float g_cat[(size_t)NN * 192];
__device__ float g_c1 [(size_t)NN * 64];
__device__ float g_c2 [(size_t)NN * 64];
__device__ float g_h3 [(size_t)NN * 64];

// ---------------- graph structure build ----------------
__global__ void zero_cnt_kernel() {
    int i = blockIdx.x * 256 + threadIdx.x;
    if (i < NN) g_cnt[i] = 0;
}

__global__ void build_bucket_kernel(const int* __restrict__ src,
                                    const int* __restrict__ dst) {
    int e = blockIdx.x * 256 + threadIdx.x;
    if (e >= EE) return;
    int d = dst[e];
    int p = atomicAdd(&g_cnt[d], 1);
    if (p < BCAP) g_bucket[(size_t)d * BCAP + p] = src[e];
}

__global__ void dinv_kernel() {
    int i = blockIdx.x * 256 + threadIdx.x;
    if (i >= NN) return;
    int c = g_cnt[i];
    float d = (float)(c > 0 ? c : 1);
    g_dinv[i] = rsqrtf(d);
}

// ---------------- dense GEMM v2: out[N,64] = relu?(X[N,KD] @ W[64,KD]^T + b) ----
// 64x64 tile per block, 256 threads = 16 rowgroups x 16 colgroups, 4x4 register
// blocking per thread. Per 4-k step: 4 LDG.128 (X, lane-broadcast) + 4 LDS.128
// (W transposed in smem, conflict-free) + 64 FFMA  -> FMA-bound.
template <int KD>
__global__ void __launch_bounds__(256) gemm64_kernel(const float* __restrict__ X,
                                                     const float* __restrict__ W,
                                                     const float* __restrict__ bias,
                                                     float* __restrict__ out,
                                                     int do_relu) {
    __shared__ float Wsh[KD * 64];          // Wsh[k*64 + c] = W[c*KD + k]
    int tid = threadIdx.x;
    for (int idx = tid; idx < KD * 64; idx += 256) {
        int k = idx >> 6, c = idx & 63;
        Wsh[idx] = W[c * KD + k];
    }
    __syncthreads();

    int cg = tid & 15;                      // col group: cols c0..c0+3
    int rg = tid >> 4;                      // row group: rows row0..row0+3
    int c0 = cg * 4;
    long row0 = (long)blockIdx.x * 64 + rg * 4;

    // clamp row pointers so tail block never reads OOB; stores are predicated
    long r0 = row0 + 0 < NN ? row0 + 0 : NN - 1;
    long r1 = row0 + 1 < NN ? row0 + 1 : NN - 1;
    long r2 = row0 + 2 < NN ? row0 + 2 : NN - 1;
    long r3 = row0 + 3 < NN ? row0 + 3 : NN - 1;
    const float* X0 = X + r0 * KD;
    const float* X1 = X + r1 * KD;
    const float* X2 = X + r2 * KD;
    const float* X3 = X + r3 * KD;

    float acc[4][4];
#pragma unroll
    for (int r = 0; r < 4; r++)
#pragma unroll
        for (int j = 0; j < 4; j++) acc[r][j] = 0.f;

#pragma unroll 4
    for (int k = 0; k < KD; k += 4) {
        float4 xv0 = *(const float4*)(X0 + k);
        float4 xv1 = *(const float4*)(X1 + k);
        float4 xv2 = *(const float4*)(X2 + k);
        float4 xv3 = *(const float4*)(X3 + k);
        float4 w0 = *(const float4*)(Wsh + (k + 0) * 64 + c0);
        float4 w1 = *(const float4*)(Wsh + (k + 1) * 64 + c0);
        float4 w2 = *(const float4*)(Wsh + (k + 2) * 64 + c0);
        float4 w3 = *(const float4*)(Wsh + (k + 3) * 64 + c0);

        const float* wp0 = (const float*)&w0;
        const float* wp1 = (const float*)&w1;
        const float* wp2 = (const float*)&w2;
        const float* wp3 = (const float*)&w3;
        float xs[4][4] = {
            {xv0.x, xv0.y, xv0.z, xv0.w},
            {xv1.x, xv1.y, xv1.z, xv1.w},
            {xv2.x, xv2.y, xv2.z, xv2.w},
            {xv3.x, xv3.y, xv3.z, xv3.w},
        };
#pragma unroll
        for (int r = 0; r < 4; r++) {
#pragma unroll
            for (int j = 0; j < 4; j++) {
                acc[r][j] = fmaf(xs[r][0], wp0[j], acc[r][j]);
                acc[r][j] = fmaf(xs[r][1], wp1[j], acc[r][j]);
                acc[r][j] = fmaf(xs[r][2], wp2[j], acc[r][j]);
                acc[r][j] = fmaf(xs[r][3], wp3[j], acc[r][j]);
            }
        }
    }

    float4 bv = *(const float4*)(bias + c0);
    const float* bp = (const float*)&bv;
#pragma unroll
    for (int r = 0; r < 4; r++) {
        long row = row0 + r;
        if (row >= NN) break;
        float4 v;
        float* vp = (float*)&v;
#pragma unroll
        for (int j = 0; j < 4; j++) {
            float t = acc[r][j] + bp[j];
            vp[j] = do_relu ? fmaxf(t, 0.f) : t;
        }
        *(float4*)(out + row * 64 + c0) = v;
    }
}

// ---------------- SpMM gather: S[n,:] = sum_{e: dst=n} y[src[e],:] ----------------
// Warp per node, float2 per lane (64 feats). No atomics; single coalesced store.
__global__ void __launch_bounds__(256) spmm_kernel() {
    int n = (blockIdx.x * 256 + threadIdx.x) >> 5;
    if (n >= NN) return;
    int lane = threadIdx.x & 31;
    int cnt = g_cnt[n];
    if (cnt > BCAP) cnt = BCAP;
    const int* bk = &g_bucket[(size_t)n * BCAP];
    const float* yb = g_y + (size_t)lane * 2;
    float2 acc  = make_float2(0.f, 0.f);
    float2 acc2 = make_float2(0.f, 0.f);
    int i = 0;
    for (; i + 1 < cnt; i += 2) {
        int s0 = bk[i], s1 = bk[i + 1];
        float2 v0 = *(const float2*)(yb + (size_t)s0 * 64);
        float2 v1 = *(const float2*)(yb + (size_t)s1 * 64);
        acc.x  += v0.x; acc.y  += v0.y;
        acc2.x += v1.x; acc2.y += v1.y;
    }
    if (i < cnt) {
        int s = bk[i];
        float2 v = *(const float2*)(yb + (size_t)s * 64);
        acc.x += v.x; acc.y += v.y;
    }
    acc.x += acc2.x; acc.y += acc2.y;
    *(float2*)(g_S + (size_t)n * 64 + lane * 2) = acc;
}

// ---------------- Chebyshev elementwise glue (re_norm == 1 simplification) ----------------
// prep: y = h * dinv ; cat[:,0:64] = h
__global__ void cheb_prep_kernel(const float* __restrict__ h) {
    int i = blockIdx.x * 256 + threadIdx.x;       // i < NN*16 (float4 units)
    int row = i >> 4, c4 = i & 15;
    float dv = g_dinv[row];
    float4 hv = ((const float4*)h)[i];
    float4 yv = make_float4(hv.x * dv, hv.y * dv, hv.z * dv, hv.w * dv);
    ((float4*)g_y)[i] = yv;
    ((float4*)g_cat)[(size_t)row * 48 + c4] = hv;
}

// mid: t1 = S*dinv ; cat[:,64:128] = -t1 ; y = t1*dinv
__global__ void cheb_mid_kernel() {
    int i = blockIdx.x * 256 + threadIdx.x;
    int row = i >> 4, c4 = i & 15;
    float dv = g_dinv[row];
    float4 sv = ((const float4*)g_S)[i];
    float4 t = make_float4(sv.x * dv, sv.y * dv, sv.z * dv, sv.w * dv);
    ((float4*)g_cat)[(size_t)row * 48 + 16 + c4] = make_float4(-t.x, -t.y, -t.z, -t.w);
    ((float4*)g_y)[i] = make_float4(t.x * dv, t.y * dv, t.z * dv, t.w * dv);
}

// post: cat[:,128:192] = 2*S*dinv - h
__global__ void cheb_post_kernel(const float* __restrict__ h) {
    int i = blockIdx.x * 256 + threadIdx.x;
    int row = i >> 4, c4 = i & 15;
    float dv2 = 2.f * g_dinv[row];
    float4 sv = ((const float4*)g_S)[i];
    float4 hv = ((const float4*)h)[i];
    ((float4*)g_cat)[(size_t)row * 48 + 32 + c4] =
        make_float4(fmaf(sv.x, dv2, -hv.x), fmaf(sv.y, dv2, -hv.y),
                    fmaf(sv.z, dv2, -hv.z), fmaf(sv.w, dv2, -hv.w));
}

// ---------------- final head: out[N,2] = X[N,64] @ W4[2,64]^T + b4 ----------------
__global__ void __launch_bounds__(256) gemm_out_kernel(const float* __restrict__ X,
                                                       const float* __restrict__ W,
                                                       const float* __restrict__ b,
                                                       float* __restrict__ out) {
    __shared__ float Wsh[128];
    __shared__ float bsh[2];
    if (threadIdx.x < 128) Wsh[threadIdx.x] = W[threadIdx.x];
    if (threadIdx.x < 2)   bsh[threadIdx.x] = b[threadIdx.x];
    __syncthreads();
    int r = blockIdx.x * 256 + threadIdx.x;
    if (r >= NN) return;
    float a0 = bsh[0], a1 = bsh[1];
    const float* xr = X + (size_t)r * 64;
#pragma unroll
    for (int k = 0; k < 64; k += 4) {
        float4 xv = *(const float4*)(xr + k);
        a0 = fmaf(xv.x, Wsh[k], fmaf(xv.y, Wsh[k + 1], fmaf(xv.z, Wsh[k + 2], fmaf(xv.w, Wsh[k + 3], a0))));
        a1 = fmaf(xv.x, Wsh[64 + k], fmaf(xv.y, Wsh[64 + k + 1], fmaf(xv.z, Wsh[64 + k + 2], fmaf(xv.w, Wsh[64 + k + 3], a1))));
    }
    out[(size_t)r * 2 + 0] = a0;
    out[(size_t)r * 2 + 1] = a1;
}

// ---------------- launch ----------------
extern "C" void kernel_launch(void* const* d_in, const int* in_sizes, int n_in,
                              void* d_out, int out_size) {
    const float* in_feat = (const float*)d_in[0];
    const int*   src     = (const int*)d_in[1];
    const int*   dst     = (const int*)d_in[2];
    const float* W1  = (const float*)d_in[3];
    const float* b1  = (const float*)d_in[4];
    const float* W2  = (const float*)d_in[5];
    const float* b2  = (const float*)d_in[6];
    const float* Wc1 = (const float*)d_in[7];
    const float* bc1 = (const float*)d_in[8];
    const float* Wc2 = (const float*)d_in[9];
    const float* bc2 = (const float*)d_in[10];
    const float* W3  = (const float*)d_in[11];
    const float* b3  = (const float*)d_in[12];
    const float* W4  = (const float*)d_in[13];
    const float* b4  = (const float*)d_in[14];
    float* out = (float*)d_out;

    float *h1, *h2, *cat, *c1, *c2, *h3;
    cudaGetSymbolAddress((void**)&h1,  g_h1);
    cudaGetSymbolAddress((void**)&h2,  g_h2);
    cudaGetSymbolAddress((void**)&cat, g_cat);
    cudaGetSymbolAddress((void**)&c1,  g_c1);
    cudaGetSymbolAddress((void**)&c2,  g_c2);
    cudaGetSymbolAddress((void**)&h3,  g_h3);

    const int GN  = (NN + 255) / 256;      // node-parallel
    const int GE  = EE / 256;              // 3125 blocks, exact
    const int GR  = (NN + 63) / 64;        // 782 blocks for gemm64 (64 rows/block)
    const int GV  = (NN * 16) / 256;       // 3125 blocks, float4 elementwise
    const int GW  = (NN * 32 + 255) / 256; // warp-per-node spmm: 6250 blocks

    // graph structure
    zero_cnt_kernel<<<GN, 256>>>();
    build_bucket_kernel<<<GE, 256>>>(src, dst);
    dinv_kernel<<<GN, 256>>>();

    // MLP front
    gemm64_kernel<128><<<GR, 256>>>(in_feat, W1, b1, h1, 1);
    gemm64_kernel<64><<<GR, 256>>>(h1, W2, b2, h2, 1);

    // ChebConv 1 (h2 -> c1)
    cheb_prep_kernel<<<GV, 256>>>(h2);
    spmm_kernel<<<GW, 256>>>();
    cheb_mid_kernel<<<GV, 256>>>();
    spmm_kernel<<<GW, 256>>>();
    cheb_post_kernel<<<GV, 256>>>(h2);
    gemm64_kernel<192><<<GR, 256>>>(cat, Wc1, bc1, c1, 1);

    // ChebConv 2 (c1 -> c2)
    cheb_prep_kernel<<<GV, 256>>>(c1);
    spmm_kernel<<<GW, 256>>>();
    cheb_mid_kernel<<<GV, 256>>>();
    spmm_kernel<<<GW, 256>>>();
    cheb_post_kernel<<<GV, 256>>>(c1);
    gemm64_kernel<192><<<GR, 256>>>(cat, Wc2, bc2, c2, 1);

    // MLP back + head
    gemm64_kernel<64><<<GR, 256>>>(c2, W3, b3, h3, 1);
    gemm_out_kernel<<<GN, 256>>>(h3, W4, b4, out);
}

// round 4
// speedup vs baseline: 5.4917x; 1.6052x over previous
#include <cuda_runtime.h>
#include <cuda_bf16.h>
#include <cstdint>

#define NN 50000
#define EE 800000
#define BCAP 128

// ---------------- scratch (static device globals; no allocation) ----------------
__device__ int   g_cnt[NN];
__device__ int   g_bucket[(size_t)NN * BCAP];
__device__ float g_dinv[NN];
__device__ float g_h1 [(size_t)NN * 64];
__device__ float g_h2 [(size_t)NN * 64];
__device__ float g_y  [(size_t)NN * 64];
__device__ float g_S  [(size_t)NN * 64];
__device__ float g_cat[(size_t)NN * 192];
__device__ float g_c1 [(size_t)NN * 64];
__device__ float g_c2 [(size_t)NN * 64];
__device__ float g_h3 [(size_t)NN * 64];

__device__ __forceinline__ uint32_t pack_bf16(float a, float b) {
    __nv_bfloat162 t = __floats2bfloat162_rn(a, b);
    return *reinterpret_cast<uint32_t*>(&t);
}

// mma.sync m16n8k16 bf16 -> f32 (baseline PTX, sm_80+; tensor pipe on sm_103)
__device__ __forceinline__ void mma16816(float* c, const uint32_t* a, uint32_t b0, uint32_t b1) {
    asm volatile(
        "mma.sync.aligned.m16n8k16.row.col.f32.bf16.bf16.f32 "
        "{%0,%1,%2,%3}, {%4,%5,%6,%7}, {%8,%9}, {%0,%1,%2,%3};"
        : "+f"(c[0]), "+f"(c[1]), "+f"(c[2]), "+f"(c[3])
        : "r"(a[0]), "r"(a[1]), "r"(a[2]), "r"(a[3]), "r"(b0), "r"(b1));
}

// ---------------- graph structure build ----------------
__global__ void zero_cnt_kernel() {
    int i = blockIdx.x * 256 + threadIdx.x;
    if (i < NN) g_cnt[i] = 0;
}

__global__ void build_bucket_kernel(const int* __restrict__ src,
                                    const int* __restrict__ dst) {
    int e = blockIdx.x * 256 + threadIdx.x;
    if (e >= EE) return;
    int d = dst[e];
    int p = atomicAdd(&g_cnt[d], 1);
    if (p < BCAP) g_bucket[(size_t)d * BCAP + p] = src[e];
}

__global__ void dinv_kernel() {
    int i = blockIdx.x * 256 + threadIdx.x;
    if (i >= NN) return;
    int c = g_cnt[i];
    float d = (float)(c > 0 ? c : 1);
    g_dinv[i] = rsqrtf(d);
}

// =========== tensor-core GEMM: out[N,64] = relu?(X[N,KD] @ W[64,KD]^T + b) ===========
// CTA = 64 rows x 64 cols, 128 threads (4 warps); warp = m16 x n64 (8 n-tiles).
// bf16 hi/lo 3-term split: D = Xh*Wh + Xl*Wh + Xh*Wl  (error ~2^-18, need 1e-3).
// Fragments for m16n8k16.row.col are contiguous bf16 pairs in row-major storage:
//   A reg = pack(A[r][k],A[r][k+1]),  B reg = pack(W[n][k],W[n][k+1])
// -> plain LDS.32, conflict-free with row pitch PW = KD/2+4 words (pitch mod 32 = 4).
template <int KD>
__global__ void __launch_bounds__(128) gemm_mma_kernel(const float* __restrict__ X,
                                                       const float* __restrict__ W,
                                                       const float* __restrict__ bias,
                                                       float* __restrict__ out,
                                                       int do_relu) {
    constexpr int PW = KD / 2 + 4;        // row pitch in u32 words
    constexpr int T_WORDS = 64 * PW;      // one 64-row split tile
    extern __shared__ uint32_t sm[];
    uint32_t* Ah = sm;
    uint32_t* Al = sm + T_WORDS;
    uint32_t* Bh = sm + 2 * T_WORDS;
    uint32_t* Bl = sm + 3 * T_WORDS;
    __shared__ float bsh[64];

    const int tid = threadIdx.x;
    const long row0 = (long)blockIdx.x * 64;
    if (tid < 64) bsh[tid] = bias[tid];

    constexpr int KQ = KD / 4;
    // ---- stage A (X rows, hi/lo split) ----
    for (int q = tid; q < 64 * KQ; q += 128) {
        int r = q / KQ, c = (q % KQ) * 4;
        long gr = row0 + r; if (gr >= NN) gr = NN - 1;
        float4 v = *(const float4*)(X + gr * KD + c);
        float xs[4] = {v.x, v.y, v.z, v.w};
        float hs[4], ls[4];
#pragma unroll
        for (int j = 0; j < 4; j++) {
            __nv_bfloat16 h = __float2bfloat16(xs[j]);
            hs[j] = __bfloat162float(h);
            ls[j] = xs[j] - hs[j];
        }
        int w = r * PW + (c >> 1);
        Ah[w]     = pack_bf16(hs[0], hs[1]);
        Ah[w + 1] = pack_bf16(hs[2], hs[3]);
        Al[w]     = pack_bf16(ls[0], ls[1]);
        Al[w + 1] = pack_bf16(ls[2], ls[3]);
    }
    // ---- stage B (W rows, hi/lo split) ----
    for (int q = tid; q < 64 * KQ; q += 128) {
        int r = q / KQ, c = (q % KQ) * 4;
        float4 v = *(const float4*)(W + (long)r * KD + c);
        float xs[4] = {v.x, v.y, v.z, v.w};
        float hs[4], ls[4];
#pragma unroll
        for (int j = 0; j < 4; j++) {
            __nv_bfloat16 h = __float2bfloat16(xs[j]);
            hs[j] = __bfloat162float(h);
            ls[j] = xs[j] - hs[j];
        }
        int w = r * PW + (c >> 1);
        Bh[w]     = pack_bf16(hs[0], hs[1]);
        Bh[w + 1] = pack_bf16(hs[2], hs[3]);
        Bl[w]     = pack_bf16(ls[0], ls[1]);
        Bl[w + 1] = pack_bf16(ls[2], ls[3]);
    }
    __syncthreads();

    const int warp = tid >> 5, lane = tid & 31;
    const int rA = lane >> 2;             // 0..7
    const int kq = lane & 3;              // k-pair within 8-wide group
    const int wrow = warp * 16;

    float acc[8][4];
#pragma unroll
    for (int nt = 0; nt < 8; nt++)
#pragma unroll
        for (int j = 0; j < 4; j++) acc[nt][j] = 0.f;

    const uint32_t* aLo = Ah + (wrow + rA) * PW + kq;
    const uint32_t* aHi = Ah + (wrow + rA + 8) * PW + kq;
    const uint32_t* alLo = Al + (wrow + rA) * PW + kq;
    const uint32_t* alHi = Al + (wrow + rA + 8) * PW + kq;

#pragma unroll
    for (int ks = 0; ks < KD / 16; ks++) {
        const int kw = ks * 8;
        uint32_t ah[4], al[4];
        ah[0] = aLo[kw];      ah[1] = aHi[kw];
        ah[2] = aLo[kw + 4];  ah[3] = aHi[kw + 4];
        al[0] = alLo[kw];     al[1] = alHi[kw];
        al[2] = alLo[kw + 4]; al[3] = alHi[kw + 4];
#pragma unroll
        for (int nt = 0; nt < 8; nt++) {
            const int bw = (nt * 8 + rA) * PW + kw + kq;
            uint32_t bh0 = Bh[bw], bh1 = Bh[bw + 4];
            uint32_t bl0 = Bl[bw], bl1 = Bl[bw + 4];
            mma16816(acc[nt], ah, bh0, bh1);
            mma16816(acc[nt], al, bh0, bh1);
            mma16816(acc[nt], ah, bl0, bl1);
        }
    }

    // ---- epilogue: c0,c1 -> row rA, cols (kq*2,+1); c2,c3 -> row rA+8 ----
    const long r_lo = row0 + wrow + rA;
    const long r_hi = r_lo + 8;
#pragma unroll
    for (int nt = 0; nt < 8; nt++) {
        int col = nt * 8 + kq * 2;
        float2 v0 = make_float2(acc[nt][0] + bsh[col], acc[nt][1] + bsh[col + 1]);
        float2 v1 = make_float2(acc[nt][2] + bsh[col], acc[nt][3] + bsh[col + 1]);
        if (do_relu) {
            v0.x = fmaxf(v0.x, 0.f); v0.y = fmaxf(v0.y, 0.f);
            v1.x = fmaxf(v1.x, 0.f); v1.y = fmaxf(v1.y, 0.f);
        }
        if (r_lo < NN) *(float2*)(out + r_lo * 64 + col) = v0;
        if (r_hi < NN) *(float2*)(out + r_hi * 64 + col) = v1;
    }
}

// ---------------- SpMM gather: S[n,:] = sum_{e: dst=n} y[src[e],:] ----------------
__global__ void __launch_bounds__(256) spmm_kernel() {
    int n = (blockIdx.x * 256 + threadIdx.x) >> 5;
    if (n >= NN) return;
    int lane = threadIdx.x & 31;
    int cnt = g_cnt[n];
    if (cnt > BCAP) cnt = BCAP;
    const int* bk = &g_bucket[(size_t)n * BCAP];
    const float* yb = g_y + (size_t)lane * 2;
    float2 acc  = make_float2(0.f, 0.f);
    float2 acc2 = make_float2(0.f, 0.f);
    int i = 0;
    for (; i + 1 < cnt; i += 2) {
        int s0 = bk[i], s1 = bk[i + 1];
        float2 v0 = *(const float2*)(yb + (size_t)s0 * 64);
        float2 v1 = *(const float2*)(yb + (size_t)s1 * 64);
        acc.x  += v0.x; acc.y  += v0.y;
        acc2.x += v1.x; acc2.y += v1.y;
    }
    if (i < cnt) {
        int s = bk[i];
        float2 v = *(const float2*)(yb + (size_t)s * 64);
        acc.x += v.x; acc.y += v.y;
    }
    acc.x += acc2.x; acc.y += acc2.y;
    *(float2*)(g_S + (size_t)n * 64 + lane * 2) = acc;
}

// ---------------- Chebyshev elementwise glue (re_norm == 1 simplification) ----------------
__global__ void cheb_prep_kernel(const float* __restrict__ h) {
    int i = blockIdx.x * 256 + threadIdx.x;
    int row = i >> 4, c4 = i & 15;
    float dv = g_dinv[row];
    float4 hv = ((const float4*)h)[i];
    float4 yv = make_float4(hv.x * dv, hv.y * dv, hv.z * dv, hv.w * dv);
    ((float4*)g_y)[i] = yv;
    ((float4*)g_cat)[(size_t)row * 48 + c4] = hv;
}

__global__ void cheb_mid_kernel() {
    int i = blockIdx.x * 256 + threadIdx.x;
    int row = i >> 4, c4 = i & 15;
    float dv = g_dinv[row];
    float4 sv = ((const float4*)g_S)[i];
    float4 t = make_float4(sv.x * dv, sv.y * dv, sv.z * dv, sv.w * dv);
    ((float4*)g_cat)[(size_t)row * 48 + 16 + c4] = make_float4(-t.x, -t.y, -t.z, -t.w);
    ((float4*)g_y)[i] = make_float4(t.x * dv, t.y * dv, t.z * dv, t.w * dv);
}

__global__ void cheb_post_kernel(const float* __restrict__ h) {
    int i = blockIdx.x * 256 + threadIdx.x;
    int row = i >> 4, c4 = i & 15;
    float dv2 = 2.f * g_dinv[row];
    float4 sv = ((const float4*)g_S)[i];
    float4 hv = ((const float4*)h)[i];
    ((float4*)g_cat)[(size_t)row * 48 + 32 + c4] =
        make_float4(fmaf(sv.x, dv2, -hv.x), fmaf(sv.y, dv2, -hv.y),
                    fmaf(sv.z, dv2, -hv.z), fmaf(sv.w, dv2, -hv.w));
}

// ---------------- final head: out[N,2] = X[N,64] @ W4[2,64]^T + b4 ----------------
__global__ void __launch_bounds__(256) gemm_out_kernel(const float* __restrict__ X,
                                                       const float* __restrict__ W,
                                                       const float* __restrict__ b,
                                                       float* __restrict__ out) {
    __shared__ float Wsh[128];
    __shared__ float bsh[2];
    if (threadIdx.x < 128) Wsh[threadIdx.x] = W[threadIdx.x];
    if (threadIdx.x < 2)   bsh[threadIdx.x] = b[threadIdx.x];
    __syncthreads();
    int r = blockIdx.x * 256 + threadIdx.x;
    if (r >= NN) return;
    float a0 = bsh[0], a1 = bsh[1];
    const float* xr = X + (size_t)r * 64;
#pragma unroll
    for (int k = 0; k < 64; k += 4) {
        float4 xv = *(const float4*)(xr + k);
        a0 = fmaf(xv.x, Wsh[k], fmaf(xv.y, Wsh[k + 1], fmaf(xv.z, Wsh[k + 2], fmaf(xv.w, Wsh[k + 3], a0))));
        a1 = fmaf(xv.x, Wsh[64 + k], fmaf(xv.y, Wsh[64 + k + 1], fmaf(xv.z, Wsh[64 + k + 2], fmaf(xv.w, Wsh[64 + k + 3], a1))));
    }
    out[(size_t)r * 2 + 0] = a0;
    out[(size_t)r * 2 + 1] = a1;
}

// ---------------- launch ----------------
static inline int gemm_smem_bytes(int kd) { return 4 * 64 * (kd / 2 + 4) * 4; }

extern "C" void kernel_launch(void* const* d_in, const int* in_sizes, int n_in,
                              void* d_out, int out_size) {
    const float* in_feat = (const float*)d_in[0];
    const int*   src     = (const int*)d_in[1];
    const int*   dst     = (const int*)d_in[2];
    const float* W1  = (const float*)d_in[3];
    const float* b1  = (const float*)d_in[4];
    const float* W2  = (const float*)d_in[5];
    const float* b2  = (const float*)d_in[6];
    const float* Wc1 = (const float*)d_in[7];
    const float* bc1 = (const float*)d_in[8];
    const float* Wc2 = (const float*)d_in[9];
    const float* bc2 = (const float*)d_in[10];
    const float* W3  = (const float*)d_in[11];
    const float* b3  = (const float*)d_in[12];
    const float* W4  = (const float*)d_in[13];
    const float* b4  = (const float*)d_in[14];
    float* out = (float*)d_out;

    float *h1, *h2, *cat, *c1, *c2, *h3;
    cudaGetSymbolAddress((void**)&h1,  g_h1);
    cudaGetSymbolAddress((void**)&h2,  g_h2);
    cudaGetSymbolAddress((void**)&cat, g_cat);
    cudaGetSymbolAddress((void**)&c1,  g_c1);
    cudaGetSymbolAddress((void**)&c2,  g_c2);
    cudaGetSymbolAddress((void**)&h3,  g_h3);

    cudaFuncSetAttribute(gemm_mma_kernel<128>, cudaFuncAttributeMaxDynamicSharedMemorySize, gemm_smem_bytes(128));
    cudaFuncSetAttribute(gemm_mma_kernel<64>,  cudaFuncAttributeMaxDynamicSharedMemorySize, gemm_smem_bytes(64));
    cudaFuncSetAttribute(gemm_mma_kernel<192>, cudaFuncAttributeMaxDynamicSharedMemorySize, gemm_smem_bytes(192));

    const int GN  = (NN + 255) / 256;
    const int GE  = EE / 256;
    const int GT  = (NN + 63) / 64;        // 782 GEMM CTAs
    const int GV  = (NN * 16) / 256;
    const int GW  = (NN * 32 + 255) / 256;

    // graph structure
    zero_cnt_kernel<<<GN, 256>>>();
    build_bucket_kernel<<<GE, 256>>>(src, dst);
    dinv_kernel<<<GN, 256>>>();

    // MLP front
    gemm_mma_kernel<128><<<GT, 128, gemm_smem_bytes(128)>>>(in_feat, W1, b1, h1, 1);
    gemm_mma_kernel<64><<<GT, 128, gemm_smem_bytes(64)>>>(h1, W2, b2, h2, 1);

    // ChebConv 1 (h2 -> c1)
    cheb_prep_kernel<<<GV, 256>>>(h2);
    spmm_kernel<<<GW, 256>>>();
    cheb_mid_kernel<<<GV, 256>>>();
    spmm_kernel<<<GW, 256>>>();
    cheb_post_kernel<<<GV, 256>>>(h2);
    gemm_mma_kernel<192><<<GT, 128, gemm_smem_bytes(192)>>>(cat, Wc1, bc1, c1, 1);

    // ChebConv 2 (c1 -> c2)
    cheb_prep_kernel<<<GV, 256>>>(c1);
    spmm_kernel<<<GW, 256>>>();
    cheb_mid_kernel<<<GV, 256>>>();
    spmm_kernel<<<GW, 256>>>();
    cheb_post_kernel<<<GV, 256>>>(c1);
    gemm_mma_kernel<192><<<GT, 128, gemm_smem_bytes(192)>>>(cat, Wc2, bc2, c2, 1);

    // MLP back + head
    gemm_mma_kernel<64><<<GT, 128, gemm_smem_bytes(64)>>>(c2, W3, b3, h3, 1);
    gemm_out_kernel<<<GN, 256>>>(h3, W4, b4, out);
}

// round 5
// speedup vs baseline: 5.9476x; 1.0830x over previous
#include <cuda_runtime.h>
#include <cuda_bf16.h>
#include <cstdint>

#define NN 50000
#define EE 800000
#define BCAP 128

// ---------------- scratch (static device globals; no allocation) ----------------
__device__ int   g_cnt[NN];
__device__ int   g_bucket[(size_t)NN * BCAP];
__device__ float g_dinv[NN];
__device__ float g_h1 [(size_t)NN * 64];
__device__ float g_h2 [(size_t)NN * 64];
__device__ float g_S1 [(size_t)NN * 64];
__device__ float g_S2 [(size_t)NN * 64];
__device__ float g_c1 [(size_t)NN * 64];
__device__ float g_c2 [(size_t)NN * 64];
__device__ float g_h3 [(size_t)NN * 64];

__device__ __forceinline__ uint32_t pack_bf16(float a, float b) {
    __nv_bfloat162 t = __floats2bfloat162_rn(a, b);
    return *reinterpret_cast<uint32_t*>(&t);
}

// mma.sync m16n8k16 bf16 -> f32 (baseline PTX, sm_80+; tensor pipe on sm_103)
__device__ __forceinline__ void mma16816(float* c, const uint32_t* a, uint32_t b0, uint32_t b1) {
    asm volatile(
        "mma.sync.aligned.m16n8k16.row.col.f32.bf16.bf16.f32 "
        "{%0,%1,%2,%3}, {%4,%5,%6,%7}, {%8,%9}, {%0,%1,%2,%3};"
        : "+f"(c[0]), "+f"(c[1]), "+f"(c[2]), "+f"(c[3])
        : "r"(a[0]), "r"(a[1]), "r"(a[2]), "r"(a[3]), "r"(b0), "r"(b1));
}

// ---------------- graph structure build ----------------
__global__ void zero_cnt_kernel() {
    int i = blockIdx.x * 256 + threadIdx.x;
    if (i < NN) g_cnt[i] = 0;
}

__global__ void build_bucket_kernel(const int* __restrict__ src,
                                    const int* __restrict__ dst) {
    int e = blockIdx.x * 256 + threadIdx.x;
    if (e >= EE) return;
    int d = dst[e];
    int p = atomicAdd(&g_cnt[d], 1);
    if (p < BCAP) g_bucket[(size_t)d * BCAP + p] = src[e];
}

__global__ void dinv_kernel() {
    int i = blockIdx.x * 256 + threadIdx.x;
    if (i >= NN) return;
    int c = g_cnt[i];
    float d = (float)(c > 0 ? c : 1);
    g_dinv[i] = rsqrtf(d);
}

// =========== tensor-core GEMM: out[N,64] = relu?(A[N,KD] @ W[64,KD]^T + b) ===========
// CTA = 64 rows x 64 cols, 256 threads (8 warps); warp = m16 x n32 (4 n-tiles).
// bf16 hi/lo 3-term split: D = Xh*Wh + Xl*Wh + Xh*Wl  (error ~2^-18, need 1e-3).
// CAT=1: A row is synthesized on the fly as [h | -S1 | 2*S2 - h] (KD must be 192),
// eliminating the concat buffer entirely.
// Fragments for m16n8k16.row.col are contiguous bf16 pairs in row-major storage ->
// plain LDS.32, conflict-free with row pitch PW = KD/2+4 words (PW mod 32 == 4).
template <int KD, int CAT>
__global__ void __launch_bounds__(256) gemm_mma_kernel(const float* __restrict__ X,
                                                       const float* __restrict__ S1,
                                                       const float* __restrict__ S2,
                                                       const float* __restrict__ W,
                                                       const float* __restrict__ bias,
                                                       float* __restrict__ out,
                                                       int do_relu) {
    constexpr int PW = KD / 2 + 4;        // row pitch in u32 words
    constexpr int T_WORDS = 64 * PW;      // one 64-row split tile
    extern __shared__ uint32_t sm[];
    uint32_t* Ah = sm;
    uint32_t* Al = sm + T_WORDS;
    uint32_t* Bh = sm + 2 * T_WORDS;
    uint32_t* Bl = sm + 3 * T_WORDS;
    __shared__ float bsh[64];

    const int tid = threadIdx.x;
    const long row0 = (long)blockIdx.x * 64;
    if (tid < 64) bsh[tid] = bias[tid];

    constexpr int KQ = KD / 4;
    // ---- stage A (hi/lo split; optionally fused Chebyshev concat) ----
    for (int q = tid; q < 64 * KQ; q += 256) {
        int r = q / KQ, c = (q % KQ) * 4;
        long gr = row0 + r; if (gr >= NN) gr = NN - 1;
        float4 v;
        if (CAT) {
            if (c < 64) {
                v = *(const float4*)(X + gr * 64 + c);
            } else if (c < 128) {
                float4 s = *(const float4*)(S1 + gr * 64 + (c - 64));
                v = make_float4(-s.x, -s.y, -s.z, -s.w);
            } else {
                float4 s = *(const float4*)(S2 + gr * 64 + (c - 128));
                float4 h = *(const float4*)(X + gr * 64 + (c - 128));
                v = make_float4(fmaf(2.f, s.x, -h.x), fmaf(2.f, s.y, -h.y),
                                fmaf(2.f, s.z, -h.z), fmaf(2.f, s.w, -h.w));
            }
        } else {
            v = *(const float4*)(X + gr * KD + c);
        }
        float xs[4] = {v.x, v.y, v.z, v.w};
        float hs[4], ls[4];
#pragma unroll
        for (int j = 0; j < 4; j++) {
            __nv_bfloat16 h = __float2bfloat16(xs[j]);
            hs[j] = __bfloat162float(h);
            ls[j] = xs[j] - hs[j];
        }
        int w = r * PW + (c >> 1);
        Ah[w]     = pack_bf16(hs[0], hs[1]);
        Ah[w + 1] = pack_bf16(hs[2], hs[3]);
        Al[w]     = pack_bf16(ls[0], ls[1]);
        Al[w + 1] = pack_bf16(ls[2], ls[3]);
    }
    // ---- stage B (W rows, hi/lo split) ----
    for (int q = tid; q < 64 * KQ; q += 256) {
        int r = q / KQ, c = (q % KQ) * 4;
        float4 v = *(const float4*)(W + (long)r * KD + c);
        float xs[4] = {v.x, v.y, v.z, v.w};
        float hs[4], ls[4];
#pragma unroll
        for (int j = 0; j < 4; j++) {
            __nv_bfloat16 h = __float2bfloat16(xs[j]);
            hs[j] = __bfloat162float(h);
            ls[j] = xs[j] - hs[j];
        }
        int w = r * PW + (c >> 1);
        Bh[w]     = pack_bf16(hs[0], hs[1]);
        Bh[w + 1] = pack_bf16(hs[2], hs[3]);
        Bl[w]     = pack_bf16(ls[0], ls[1]);
        Bl[w + 1] = pack_bf16(ls[2], ls[3]);
    }
    __syncthreads();

    const int warp = tid >> 5, lane = tid & 31;
    const int rA = lane >> 2;             // 0..7
    const int kq = lane & 3;              // k-pair within 8-wide group
    const int wrow = (warp & 3) * 16;     // row group
    const int nt0 = (warp >> 2) * 4;      // n-tile base (4 tiles of n8)

    float acc[4][4];
#pragma unroll
    for (int nt = 0; nt < 4; nt++)
#pragma unroll
        for (int j = 0; j < 4; j++) acc[nt][j] = 0.f;

    const uint32_t* aLo  = Ah + (wrow + rA) * PW + kq;
    const uint32_t* aHi  = Ah + (wrow + rA + 8) * PW + kq;
    const uint32_t* alLo = Al + (wrow + rA) * PW + kq;
    const uint32_t* alHi = Al + (wrow + rA + 8) * PW + kq;

#pragma unroll
    for (int ks = 0; ks < KD / 16; ks++) {
        const int kw = ks * 8;
        uint32_t ah[4], al[4];
        ah[0] = aLo[kw];      ah[1] = aHi[kw];
        ah[2] = aLo[kw + 4];  ah[3] = aHi[kw + 4];
        al[0] = alLo[kw];     al[1] = alHi[kw];
        al[2] = alLo[kw + 4]; al[3] = alHi[kw + 4];
#pragma unroll
        for (int nt = 0; nt < 4; nt++) {
            const int bw = ((nt0 + nt) * 8 + rA) * PW + kw + kq;
            uint32_t bh0 = Bh[bw], bh1 = Bh[bw + 4];
            uint32_t bl0 = Bl[bw], bl1 = Bl[bw + 4];
            mma16816(acc[nt], ah, bh0, bh1);
            mma16816(acc[nt], al, bh0, bh1);
            mma16816(acc[nt], ah, bl0, bl1);
        }
    }

    // ---- epilogue: c0,c1 -> row rA, cols (kq*2,+1); c2,c3 -> row rA+8 ----
    const long r_lo = row0 + wrow + rA;
    const long r_hi = r_lo + 8;
#pragma unroll
    for (int nt = 0; nt < 4; nt++) {
        int col = (nt0 + nt) * 8 + kq * 2;
        float2 v0 = make_float2(acc[nt][0] + bsh[col], acc[nt][1] + bsh[col + 1]);
        float2 v1 = make_float2(acc[nt][2] + bsh[col], acc[nt][3] + bsh[col + 1]);
        if (do_relu) {
            v0.x = fmaxf(v0.x, 0.f); v0.y = fmaxf(v0.y, 0.f);
            v1.x = fmaxf(v1.x, 0.f); v1.y = fmaxf(v1.y, 0.f);
        }
        if (r_lo < NN) *(float2*)(out + r_lo * 64 + col) = v0;
        if (r_hi < NN) *(float2*)(out + r_hi * 64 + col) = v1;
    }
}

// ------------- normalized SpMM: Sout[n,:] = dinv[n] * sum_{e: dst=n} dinv[s]*Xin[s,:] -------------
// Warp per node, float2 per lane. dinv applied inline on both sides (no prep pass).
__global__ void __launch_bounds__(256) spmm_norm_kernel(const float* __restrict__ Xin,
                                                        float* __restrict__ Sout) {
    int n = (blockIdx.x * 256 + threadIdx.x) >> 5;
    if (n >= NN) return;
    int lane = threadIdx.x & 31;
    int cnt = g_cnt[n];
    if (cnt > BCAP) cnt = BCAP;
    const int* bk = &g_bucket[(size_t)n * BCAP];
    const float* xb = Xin + (size_t)lane * 2;
    float2 acc  = make_float2(0.f, 0.f);
    float2 acc2 = make_float2(0.f, 0.f);
    int i = 0;
    for (; i + 1 < cnt; i += 2) {
        int s0 = bk[i], s1 = bk[i + 1];
        float d0 = g_dinv[s0], d1 = g_dinv[s1];
        float2 v0 = *(const float2*)(xb + (size_t)s0 * 64);
        float2 v1 = *(const float2*)(xb + (size_t)s1 * 64);
        acc.x  = fmaf(v0.x, d0, acc.x);  acc.y  = fmaf(v0.y, d0, acc.y);
        acc2.x = fmaf(v1.x, d1, acc2.x); acc2.y = fmaf(v1.y, d1, acc2.y);
    }
    if (i < cnt) {
        int s = bk[i];
        float ds = g_dinv[s];
        float2 v = *(const float2*)(xb + (size_t)s * 64);
        acc.x = fmaf(v.x, ds, acc.x); acc.y = fmaf(v.y, ds, acc.y);
    }
    float dn = g_dinv[n];
    acc.x = (acc.x + acc2.x) * dn;
    acc.y = (acc.y + acc2.y) * dn;
    *(float2*)(Sout + (size_t)n * 64 + lane * 2) = acc;
}

// ---------------- final head: out[N,2] = X[N,64] @ W4[2,64]^T + b4 ----------------
__global__ void __launch_bounds__(256) gemm_out_kernel(const float* __restrict__ X,
                                                       const float* __restrict__ W,
                                                       const float* __restrict__ b,
                                                       float* __restrict__ out) {
    __shared__ float Wsh[128];
    __shared__ float bsh[2];
    if (threadIdx.x < 128) Wsh[threadIdx.x] = W[threadIdx.x];
    if (threadIdx.x < 2)   bsh[threadIdx.x] = b[threadIdx.x];
    __syncthreads();
    int r = blockIdx.x * 256 + threadIdx.x;
    if (r >= NN) return;
    float a0 = bsh[0], a1 = bsh[1];
    const float* xr = X + (size_t)r * 64;
#pragma unroll
    for (int k = 0; k < 64; k += 4) {
        float4 xv = *(const float4*)(xr + k);
        a0 = fmaf(xv.x, Wsh[k], fmaf(xv.y, Wsh[k + 1], fmaf(xv.z, Wsh[k + 2], fmaf(xv.w, Wsh[k + 3], a0))));
        a1 = fmaf(xv.x, Wsh[64 + k], fmaf(xv.y, Wsh[64 + k + 1], fmaf(xv.z, Wsh[64 + k + 2], fmaf(xv.w, Wsh[64 + k + 3], a1))));
    }
    out[(size_t)r * 2 + 0] = a0;
    out[(size_t)r * 2 + 1] = a1;
}

// ---------------- launch ----------------
static inline int gemm_smem_bytes(int kd) { return 4 * 64 * (kd / 2 + 4) * 4; }

extern "C" void kernel_launch(void* const* d_in, const int* in_sizes, int n_in,
                              void* d_out, int out_size) {
    const float* in_feat = (const float*)d_in[0];
    const int*   src     = (const int*)d_in[1];
    const int*   dst     = (const int*)d_in[2];
    const float* W1  = (const float*)d_in[3];
    const float* b1  = (const float*)d_in[4];
    const float* W2  = (const float*)d_in[5];
    const float* b2  = (const float*)d_in[6];
    const float* Wc1 = (const float*)d_in[7];
    const float* bc1 = (const float*)d_in[8];
    const float* Wc2 = (const float*)d_in[9];
    const float* bc2 = (const float*)d_in[10];
    const float* W3  = (const float*)d_in[11];
    const float* b3  = (const float*)d_in[12];
    const float* W4  = (const float*)d_in[13];
    const float* b4  = (const float*)d_in[14];
    float* out = (float*)d_out;

    float *h1, *h2, *S1, *S2, *c1, *c2, *h3;
    cudaGetSymbolAddress((void**)&h1, g_h1);
    cudaGetSymbolAddress((void**)&h2, g_h2);
    cudaGetSymbolAddress((void**)&S1, g_S1);
    cudaGetSymbolAddress((void**)&S2, g_S2);
    cudaGetSymbolAddress((void**)&c1, g_c1);
    cudaGetSymbolAddress((void**)&c2, g_c2);
    cudaGetSymbolAddress((void**)&h3, g_h3);

    cudaFuncSetAttribute(gemm_mma_kernel<128,0>, cudaFuncAttributeMaxDynamicSharedMemorySize, gemm_smem_bytes(128));
    cudaFuncSetAttribute(gemm_mma_kernel<64,0>,  cudaFuncAttributeMaxDynamicSharedMemorySize, gemm_smem_bytes(64));
    cudaFuncSetAttribute(gemm_mma_kernel<192,1>, cudaFuncAttributeMaxDynamicSharedMemorySize, gemm_smem_bytes(192));

    const int GN  = (NN + 255) / 256;
    const int GE  = EE / 256;
    const int GT  = (NN + 63) / 64;        // 782 GEMM CTAs
    const int GW  = (NN * 32 + 255) / 256; // warp-per-node spmm

    // graph structure
    zero_cnt_kernel<<<GN, 256>>>();
    build_bucket_kernel<<<GE, 256>>>(src, dst);
    dinv_kernel<<<GN, 256>>>();

    // MLP front
    gemm_mma_kernel<128,0><<<GT, 256, gemm_smem_bytes(128)>>>(in_feat, nullptr, nullptr, W1, b1, h1, 1);
    gemm_mma_kernel<64,0><<<GT, 256, gemm_smem_bytes(64)>>>(h1, nullptr, nullptr, W2, b2, h2, 1);

    // ChebConv 1: S1 = a_norm(h2), S2 = a_norm(S1), c1 = relu([h2|-S1|2S2-h2] @ Wc1^T + bc1)
    spmm_norm_kernel<<<GW, 256>>>(h2, S1);
    spmm_norm_kernel<<<GW, 256>>>(S1, S2);
    gemm_mma_kernel<192,1><<<GT, 256, gemm_smem_bytes(192)>>>(h2, S1, S2, Wc1, bc1, c1, 1);

    // ChebConv 2
    spmm_norm_kernel<<<GW, 256>>>(c1, S1);
    spmm_norm_kernel<<<GW, 256>>>(S1, S2);
    gemm_mma_kernel<192,1><<<GT, 256, gemm_smem_bytes(192)>>>(c1, S1, S2, Wc2, bc2, c2, 1);

    // MLP back + head
    gemm_mma_kernel<64,0><<<GT, 256, gemm_smem_bytes(64)>>>(c2, nullptr, nullptr, W3, b3, h3, 1);
    gemm_out_kernel<<<GN, 256>>>(h3, W4, b4, out);
}

// round 6
// speedup vs baseline: 6.0455x; 1.0164x over previous
#include <cuda_runtime.h>
#include <cuda_bf16.h>
#include <cstdint>

#define NN 50000
#define EE 800000
#define BCAP 128

// ---------------- scratch (static device globals; no allocation) ----------------
__device__ int   g_cnt[NN];
__device__ int   g_bucket[(size_t)NN * BCAP];
__device__ float g_dinv[NN];
__device__ float g_h1 [(size_t)NN * 64];
__device__ float g_h2 [(size_t)NN * 64];
__device__ float g_S1 [(size_t)NN * 64];
__device__ float g_S2 [(size_t)NN * 64];
__device__ float g_c1 [(size_t)NN * 64];
__device__ float g_c2 [(size_t)NN * 64];
__device__ float g_h3 [(size_t)NN * 64];

__device__ __forceinline__ uint32_t pack_bf16(float a, float b) {
    __nv_bfloat162 t = __floats2bfloat162_rn(a, b);
    return *reinterpret_cast<uint32_t*>(&t);
}

// mma.sync m16n8k16 bf16 -> f32 (baseline PTX, sm_80+; tensor pipe on sm_103)
__device__ __forceinline__ void mma16816(float* c, const uint32_t* a, uint32_t b0, uint32_t b1) {
    asm volatile(
        "mma.sync.aligned.m16n8k16.row.col.f32.bf16.bf16.f32 "
        "{%0,%1,%2,%3}, {%4,%5,%6,%7}, {%8,%9}, {%0,%1,%2,%3};"
        : "+f"(c[0]), "+f"(c[1]), "+f"(c[2]), "+f"(c[3])
        : "r"(a[0]), "r"(a[1]), "r"(a[2]), "r"(a[3]), "r"(b0), "r"(b1));
}

__device__ __forceinline__ void ldsm_x4(uint32_t addr, uint32_t* r) {
    asm volatile("ldmatrix.sync.aligned.m8n8.x4.shared.b16 {%0,%1,%2,%3}, [%4];"
                 : "=r"(r[0]), "=r"(r[1]), "=r"(r[2]), "=r"(r[3]) : "r"(addr));
}
__device__ __forceinline__ void ldsm_x2(uint32_t addr, uint32_t* r) {
    asm volatile("ldmatrix.sync.aligned.m8n8.x2.shared.b16 {%0,%1}, [%2];"
                 : "=r"(r[0]), "=r"(r[1]) : "r"(addr));
}

// ---------------- graph structure build ----------------
__global__ void zero_cnt_kernel() {
    int i = blockIdx.x * 256 + threadIdx.x;
    if (i < NN) g_cnt[i] = 0;
}

__global__ void build_bucket_kernel(const int* __restrict__ src,
                                    const int* __restrict__ dst) {
    int e = blockIdx.x * 256 + threadIdx.x;
    if (e >= EE) return;
    int d = dst[e];
    int p = atomicAdd(&g_cnt[d], 1);
    if (p < BCAP) g_bucket[(size_t)d * BCAP + p] = src[e];
}

__global__ void dinv_kernel() {
    int i = blockIdx.x * 256 + threadIdx.x;
    if (i >= NN) return;
    int c = g_cnt[i];
    float d = (float)(c > 0 ? c : 1);
    g_dinv[i] = rsqrtf(d);
}

// =========== tensor-core GEMM: out[N,64] = relu?(A[N,KD] @ W[64,KD]^T + b) ===========
// CTA = 64 rows x 64 cols, 256 threads (8 warps); warp = m16 x n32 (4 n-tiles).
// bf16 hi/lo 3-term split: D = Xh*Wh + Xl*Wh + Xh*Wl.
// All fragment loads via ldmatrix (LDSM): A hi/lo = 2x ldmatrix.x4 per k16 step,
// B = ldmatrix.x2 per n-tile per split -> 10 LDSM + 12 HMMA per step per warp.
// Pitch PW = KD/2+4 words (== 4 mod 32) -> each LDSM phase hits distinct banks.
// CAT=1: A row synthesized on the fly as [h | -S1 | 2*S2 - h] (KD == 192).
template <int KD, int CAT>
__global__ void __launch_bounds__(256) gemm_mma_kernel(const float* __restrict__ X,
                                                       const float* __restrict__ S1,
                                                       const float* __restrict__ S2,
                                                       const float* __restrict__ W,
                                                       const float* __restrict__ bias,
                                                       float* __restrict__ out,
                                                       int do_relu) {
    constexpr int PW = KD / 2 + 4;        // row pitch in u32 words
    constexpr int T_WORDS = 64 * PW;      // one 64-row split tile
    extern __shared__ uint32_t sm[];
    uint32_t* Ah = sm;
    uint32_t* Al = sm + T_WORDS;
    uint32_t* Bh = sm + 2 * T_WORDS;
    uint32_t* Bl = sm + 3 * T_WORDS;
    __shared__ float bsh[64];

    const int tid = threadIdx.x;
    const long row0 = (long)blockIdx.x * 64;
    if (tid < 64) bsh[tid] = bias[tid];

    constexpr int KQ = KD / 4;
    // ---- stage A (hi/lo split; optionally fused Chebyshev concat) ----
    for (int q = tid; q < 64 * KQ; q += 256) {
        int r = q / KQ, c = (q % KQ) * 4;
        long gr = row0 + r; if (gr >= NN) gr = NN - 1;
        float4 v;
        if (CAT) {
            if (c < 64) {
                v = *(const float4*)(X + gr * 64 + c);
            } else if (c < 128) {
                float4 s = *(const float4*)(S1 + gr * 64 + (c - 64));
                v = make_float4(-s.x, -s.y, -s.z, -s.w);
            } else {
                float4 s = *(const float4*)(S2 + gr * 64 + (c - 128));
                float4 h = *(const float4*)(X + gr * 64 + (c - 128));
                v = make_float4(fmaf(2.f, s.x, -h.x), fmaf(2.f, s.y, -h.y),
                                fmaf(2.f, s.z, -h.z), fmaf(2.f, s.w, -h.w));
            }
        } else {
            v = *(const float4*)(X + gr * KD + c);
        }
        float xs[4] = {v.x, v.y, v.z, v.w};
        float hs[4], ls[4];
#pragma unroll
        for (int j = 0; j < 4; j++) {
            __nv_bfloat16 h = __float2bfloat16(xs[j]);
            hs[j] = __bfloat162float(h);
            ls[j] = xs[j] - hs[j];
        }
        int w = r * PW + (c >> 1);
        Ah[w]     = pack_bf16(hs[0], hs[1]);
        Ah[w + 1] = pack_bf16(hs[2], hs[3]);
        Al[w]     = pack_bf16(ls[0], ls[1]);
        Al[w + 1] = pack_bf16(ls[2], ls[3]);
    }
    // ---- stage B (W rows, hi/lo split) ----
    for (int q = tid; q < 64 * KQ; q += 256) {
        int r = q / KQ, c = (q % KQ) * 4;
        float4 v = *(const float4*)(W + (long)r * KD + c);
        float xs[4] = {v.x, v.y, v.z, v.w};
        float hs[4], ls[4];
#pragma unroll
        for (int j = 0; j < 4; j++) {
            __nv_bfloat16 h = __float2bfloat16(xs[j]);
            hs[j] = __bfloat162float(h);
            ls[j] = xs[j] - hs[j];
        }
        int w = r * PW + (c >> 1);
        Bh[w]     = pack_bf16(hs[0], hs[1]);
        Bh[w + 1] = pack_bf16(hs[2], hs[3]);
        Bl[w]     = pack_bf16(ls[0], ls[1]);
        Bl[w + 1] = pack_bf16(ls[2], ls[3]);
    }
    __syncthreads();

    const int warp = tid >> 5, lane = tid & 31;
    const int wrow = (warp & 3) * 16;     // row group
    const int nt0 = (warp >> 2) * 4;      // n-tile base (4 tiles of n8)

    float acc[4][4];
#pragma unroll
    for (int nt = 0; nt < 4; nt++)
#pragma unroll
        for (int j = 0; j < 4; j++) acc[nt][j] = 0.f;

    // ---- LDSM addresses ----
    const uint32_t smbase = (uint32_t)__cvta_generic_to_shared(sm);
    // A x4: m = lane>>3: M0 rows+0 w+0, M1 rows+8 w+0, M2 rows+0 w+4, M3 rows+8 w+4
    const int mA = lane >> 3;
    const uint32_t aoffw = (uint32_t)((wrow + (lane & 7) + (mA & 1) * 8) * PW + (mA >> 1) * 4);
    const uint32_t aHaddr = smbase + aoffw * 4;
    const uint32_t aLaddr = aHaddr + T_WORDS * 4;
    // B x2 (lanes 0-15): M0 rows n0+(l&7) w+0, M1 same rows w+4
    const int l15 = lane & 15;
    uint32_t bHaddr[4], bLaddr[4];
#pragma unroll
    for (int nt = 0; nt < 4; nt++) {
        uint32_t boffw = (uint32_t)(((nt0 + nt) * 8 + (l15 & 7)) * PW + (l15 >> 3) * 4);
        bHaddr[nt] = smbase + (2 * T_WORDS + boffw) * 4;
        bLaddr[nt] = bHaddr[nt] + T_WORDS * 4;
    }

#pragma unroll
    for (int ks = 0; ks < KD / 16; ks++) {
        const uint32_t kb = (uint32_t)ks * 32;   // 8 words per k16 step
        uint32_t ah[4], al[4];
        ldsm_x4(aHaddr + kb, ah);
        ldsm_x4(aLaddr + kb, al);
#pragma unroll
        for (int nt = 0; nt < 4; nt++) {
            uint32_t bh[2], bl[2];
            ldsm_x2(bHaddr[nt] + kb, bh);
            ldsm_x2(bLaddr[nt] + kb, bl);
            mma16816(acc[nt], ah, bh[0], bh[1]);
            mma16816(acc[nt], al, bh[0], bh[1]);
            mma16816(acc[nt], ah, bl[0], bl[1]);
        }
    }

    // ---- epilogue: c0,c1 -> row rA, cols (kq*2,+1); c2,c3 -> row rA+8 ----
    const int rA = lane >> 2;
    const int kq = lane & 3;
    const long r_lo = row0 + wrow + rA;
    const long r_hi = r_lo + 8;
#pragma unroll
    for (int nt = 0; nt < 4; nt++) {
        int col = (nt0 + nt) * 8 + kq * 2;
        float2 v0 = make_float2(acc[nt][0] + bsh[col], acc[nt][1] + bsh[col + 1]);
        float2 v1 = make_float2(acc[nt][2] + bsh[col], acc[nt][3] + bsh[col + 1]);
        if (do_relu) {
            v0.x = fmaxf(v0.x, 0.f); v0.y = fmaxf(v0.y, 0.f);
            v1.x = fmaxf(v1.x, 0.f); v1.y = fmaxf(v1.y, 0.f);
        }
        if (r_lo < NN) *(float2*)(out + r_lo * 64 + col) = v0;
        if (r_hi < NN) *(float2*)(out + r_hi * 64 + col) = v1;
    }
}

// ------------- normalized SpMM: Sout[n,:] = dinv[n] * sum_{e: dst=n} dinv[s]*Xin[s,:] -------------
__global__ void __launch_bounds__(256) spmm_norm_kernel(const float* __restrict__ Xin,
                                                        float* __restrict__ Sout) {
    int n = (blockIdx.x * 256 + threadIdx.x) >> 5;
    if (n >= NN) return;
    int lane = threadIdx.x & 31;
    int cnt = g_cnt[n];
    if (cnt > BCAP) cnt = BCAP;
    const int* bk = &g_bucket[(size_t)n * BCAP];
    const float* xb = Xin + (size_t)lane * 2;
    float2 acc  = make_float2(0.f, 0.f);
    float2 acc2 = make_float2(0.f, 0.f);
    int i = 0;
    for (; i + 1 < cnt; i += 2) {
        int s0 = bk[i], s1 = bk[i + 1];
        float d0 = g_dinv[s0], d1 = g_dinv[s1];
        float2 v0 = *(const float2*)(xb + (size_t)s0 * 64);
        float2 v1 = *(const float2*)(xb + (size_t)s1 * 64);
        acc.x  = fmaf(v0.x, d0, acc.x);  acc.y  = fmaf(v0.y, d0, acc.y);
        acc2.x = fmaf(v1.x, d1, acc2.x); acc2.y = fmaf(v1.y, d1, acc2.y);
    }
    if (i < cnt) {
        int s = bk[i];
        float ds = g_dinv[s];
        float2 v = *(const float2*)(xb + (size_t)s * 64);
        acc.x = fmaf(v.x, ds, acc.x); acc.y = fmaf(v.y, ds, acc.y);
    }
    float dn = g_dinv[n];
    acc.x = (acc.x + acc2.x) * dn;
    acc.y = (acc.y + acc2.y) * dn;
    *(float2*)(Sout + (size_t)n * 64 + lane * 2) = acc;
}

// ---------------- final head: out[N,2] = X[N,64] @ W4[2,64]^T + b4 ----------------
__global__ void __launch_bounds__(256) gemm_out_kernel(const float* __restrict__ X,
                                                       const float* __restrict__ W,
                                                       const float* __restrict__ b,
                                                       float* __restrict__ out) {
    __shared__ float Wsh[128];
    __shared__ float bsh[2];
    if (threadIdx.x < 128) Wsh[threadIdx.x] = W[threadIdx.x];
    if (threadIdx.x < 2)   bsh[threadIdx.x] = b[threadIdx.x];
    __syncthreads();
    int r = blockIdx.x * 256 + threadIdx.x;
    if (r >= NN) return;
    float a0 = bsh[0], a1 = bsh[1];
    const float* xr = X + (size_t)r * 64;
#pragma unroll
    for (int k = 0; k < 64; k += 4) {
        float4 xv = *(const float4*)(xr + k);
        a0 = fmaf(xv.x, Wsh[k], fmaf(xv.y, Wsh[k + 1], fmaf(xv.z, Wsh[k + 2], fmaf(xv.w, Wsh[k + 3], a0))));
        a1 = fmaf(xv.x, Wsh[64 + k], fmaf(xv.y, Wsh[64 + k + 1], fmaf(xv.z, Wsh[64 + k + 2], fmaf(xv.w, Wsh[64 + k + 3], a1))));
    }
    out[(size_t)r * 2 + 0] = a0;
    out[(size_t)r * 2 + 1] = a1;
}

// ---------------- launch ----------------
static inline int gemm_smem_bytes(int kd) { return 4 * 64 * (kd / 2 + 4) * 4; }

extern "C" void kernel_launch(void* const* d_in, const int* in_sizes, int n_in,
                              void* d_out, int out_size) {
    const float* in_feat = (const float*)d_in[0];
    const int*   src     = (const int*)d_in[1];
    const int*   dst     = (const int*)d_in[2];
    const float* W1  = (const float*)d_in[3];
    const float* b1  = (const float*)d_in[4];
    const float* W2  = (const float*)d_in[5];
    const float* b2  = (const float*)d_in[6];
    const float* Wc1 = (const float*)d_in[7];
    const float* bc1 = (const float*)d_in[8];
    const float* Wc2 = (const float*)d_in[9];
    const float* bc2 = (const float*)d_in[10];
    const float* W3  = (const float*)d_in[11];
    const float* b3  = (const float*)d_in[12];
    const float* W4  = (const float*)d_in[13];
    const float* b4  = (const float*)d_in[14];
    float* out = (float*)d_out;

    float *h1, *h2, *S1, *S2, *c1, *c2, *h3;
    cudaGetSymbolAddress((void**)&h1, g_h1);
    cudaGetSymbolAddress((void**)&h2, g_h2);
    cudaGetSymbolAddress((void**)&S1, g_S1);
    cudaGetSymbolAddress((void**)&S2, g_S2);
    cudaGetSymbolAddress((void**)&c1, g_c1);
    cudaGetSymbolAddress((void**)&c2, g_c2);
    cudaGetSymbolAddress((void**)&h3, g_h3);

    cudaFuncSetAttribute(gemm_mma_kernel<128,0>, cudaFuncAttributeMaxDynamicSharedMemorySize, gemm_smem_bytes(128));
    cudaFuncSetAttribute(gemm_mma_kernel<64,0>,  cudaFuncAttributeMaxDynamicSharedMemorySize, gemm_smem_bytes(64));
    cudaFuncSetAttribute(gemm_mma_kernel<192,1>, cudaFuncAttributeMaxDynamicSharedMemorySize, gemm_smem_bytes(192));

    const int GN  = (NN + 255) / 256;
    const int GE  = EE / 256;
    const int GT  = (NN + 63) / 64;        // 782 GEMM CTAs
    const int GW  = (NN * 32 + 255) / 256; // warp-per-node spmm

    // graph structure
    zero_cnt_kernel<<<GN, 256>>>();
    build_bucket_kernel<<<GE, 256>>>(src, dst);
    dinv_kernel<<<GN, 256>>>();

    // MLP front
    gemm_mma_kernel<128,0><<<GT, 256, gemm_smem_bytes(128)>>>(in_feat, nullptr, nullptr, W1, b1, h1, 1);
    gemm_mma_kernel<64,0><<<GT, 256, gemm_smem_bytes(64)>>>(h1, nullptr, nullptr, W2, b2, h2, 1);

    // ChebConv 1: S1 = a_norm(h2), S2 = a_norm(S1), c1 = relu([h2|-S1|2S2-h2] @ Wc1^T + bc1)
    spmm_norm_kernel<<<GW, 256>>>(h2, S1);
    spmm_norm_kernel<<<GW, 256>>>(S1, S2);
    gemm_mma_kernel<192,1><<<GT, 256, gemm_smem_bytes(192)>>>(h2, S1, S2, Wc1, bc1, c1, 1);

    // ChebConv 2
    spmm_norm_kernel<<<GW, 256>>>(c1, S1);
    spmm_norm_kernel<<<GW, 256>>>(S1, S2);
    gemm_mma_kernel<192,1><<<GT, 256, gemm_smem_bytes(192)>>>(c1, S1, S2, Wc2, bc2, c2, 1);

    // MLP back + head
    gemm_mma_kernel<64,0><<<GT, 256, gemm_smem_bytes(64)>>>(c2, nullptr, nullptr, W3, b3, h3, 1);
    gemm_out_kernel<<<GN, 256>>>(h3, W4, b4, out);
}

// round 7
// speedup vs baseline: 6.3269x; 1.0466x over previous
#include <cuda_runtime.h>
#include <cuda_bf16.h>
#include <cstdint>

#define NN 50000
#define EE 800000
#define BCAP 128

// ---------------- scratch (static device globals; no allocation) ----------------
__device__ int   g_cnt[NN];
__device__ int   g_bucket[(size_t)NN * BCAP];
__device__ float g_dinv[NN];
__device__ float g_h1 [(size_t)NN * 64];
__device__ float g_h2 [(size_t)NN * 64];
__device__ float g_S1 [(size_t)NN * 64];
__device__ float g_S2 [(size_t)NN * 64];
__device__ float g_c1 [(size_t)NN * 64];
__device__ float g_c2 [(size_t)NN * 64];
__device__ float g_h3 [(size_t)NN * 64];

__device__ __forceinline__ uint32_t pack_bf16(float a, float b) {
    __nv_bfloat162 t = __floats2bfloat162_rn(a, b);
    return *reinterpret_cast<uint32_t*>(&t);
}

// mma.sync m16n8k16 bf16 -> f32 (baseline PTX, sm_80+; tensor pipe on sm_103)
__device__ __forceinline__ void mma16816(float* c, const uint32_t* a, uint32_t b0, uint32_t b1) {
    asm volatile(
        "mma.sync.aligned.m16n8k16.row.col.f32.bf16.bf16.f32 "
        "{%0,%1,%2,%3}, {%4,%5,%6,%7}, {%8,%9}, {%0,%1,%2,%3};"
        : "+f"(c[0]), "+f"(c[1]), "+f"(c[2]), "+f"(c[3])
        : "r"(a[0]), "r"(a[1]), "r"(a[2]), "r"(a[3]), "r"(b0), "r"(b1));
}

__device__ __forceinline__ void ldsm_x4(uint32_t addr, uint32_t* r) {
    asm volatile("ldmatrix.sync.aligned.m8n8.x4.shared.b16 {%0,%1,%2,%3}, [%4];"
                 : "=r"(r[0]), "=r"(r[1]), "=r"(r[2]), "=r"(r[3]) : "r"(addr));
}
__device__ __forceinline__ void ldsm_x2(uint32_t addr, uint32_t* r) {
    asm volatile("ldmatrix.sync.aligned.m8n8.x2.shared.b16 {%0,%1}, [%2];"
                 : "=r"(r[0]), "=r"(r[1]) : "r"(addr));
}

// ---------------- graph structure build ----------------
__global__ void zero_cnt_kernel() {
    int i = blockIdx.x * 256 + threadIdx.x;
    if (i < NN) g_cnt[i] = 0;
}

__global__ void build_bucket_kernel(const int* __restrict__ src,
                                    const int* __restrict__ dst) {
    int e = blockIdx.x * 256 + threadIdx.x;
    if (e >= EE) return;
    int d = dst[e];
    int p = atomicAdd(&g_cnt[d], 1);
    if (p < BCAP) g_bucket[(size_t)d * BCAP + p] = src[e];
}

__global__ void dinv_kernel() {
    int i = blockIdx.x * 256 + threadIdx.x;
    if (i >= NN) return;
    int c = g_cnt[i];
    float d = (float)(c > 0 ? c : 1);
    g_dinv[i] = rsqrtf(d);
}

// =========== tensor-core GEMM: out[N,64] = relu?(A[N,KD] @ W[64,KD]^T + b) ===========
// CTA = 128 rows x 64 cols, 512 threads (16 warps); warp = m16 x n32 (4 n-tiles).
// bf16 hi/lo 3-term split: D = Xh*Wh + Xl*Wh + Xh*Wl.
// Fragments via ldmatrix. Pitch PW = KD/2+4 words (== 4 mod 32) -> conflict-free.
// CAT=1: A row synthesized on the fly as [h | -S1 | 2*S2 - h] (KD == 192).
template <int KD, int CAT>
__global__ void __launch_bounds__(512) gemm_mma_kernel(const float* __restrict__ X,
                                                       const float* __restrict__ S1,
                                                       const float* __restrict__ S2,
                                                       const float* __restrict__ W,
                                                       const float* __restrict__ bias,
                                                       float* __restrict__ out,
                                                       int do_relu) {
    constexpr int PW = KD / 2 + 4;        // row pitch in u32 words
    constexpr int T_A = 128 * PW;         // A split tile words
    constexpr int T_B = 64 * PW;          // B split tile words
    extern __shared__ uint32_t sm[];
    uint32_t* Ah = sm;
    uint32_t* Al = sm + T_A;
    uint32_t* Bh = sm + 2 * T_A;
    uint32_t* Bl = sm + 2 * T_A + T_B;
    __shared__ float bsh[64];

    const int tid = threadIdx.x;
    const long row0 = (long)blockIdx.x * 128;
    if (tid < 64) bsh[tid] = bias[tid];

    constexpr int KQ = KD / 4;
    // ---- stage A (hi/lo split; optionally fused Chebyshev concat) ----
    for (int q = tid; q < 128 * KQ; q += 512) {
        int r = q / KQ, c = (q % KQ) * 4;
        long gr = row0 + r; if (gr >= NN) gr = NN - 1;
        float4 v;
        if (CAT) {
            if (c < 64) {
                v = *(const float4*)(X + gr * 64 + c);
            } else if (c < 128) {
                float4 s = *(const float4*)(S1 + gr * 64 + (c - 64));
                v = make_float4(-s.x, -s.y, -s.z, -s.w);
            } else {
                float4 s = *(const float4*)(S2 + gr * 64 + (c - 128));
                float4 h = *(const float4*)(X + gr * 64 + (c - 128));
                v = make_float4(fmaf(2.f, s.x, -h.x), fmaf(2.f, s.y, -h.y),
                                fmaf(2.f, s.z, -h.z), fmaf(2.f, s.w, -h.w));
            }
        } else {
            v = *(const float4*)(X + gr * KD + c);
        }
        float xs[4] = {v.x, v.y, v.z, v.w};
        float hs[4], ls[4];
#pragma unroll
        for (int j = 0; j < 4; j++) {
            __nv_bfloat16 h = __float2bfloat16(xs[j]);
            hs[j] = __bfloat162float(h);
            ls[j] = xs[j] - hs[j];
        }
        int w = r * PW + (c >> 1);
        Ah[w]     = pack_bf16(hs[0], hs[1]);
        Ah[w + 1] = pack_bf16(hs[2], hs[3]);
        Al[w]     = pack_bf16(ls[0], ls[1]);
        Al[w + 1] = pack_bf16(ls[2], ls[3]);
    }
    // ---- stage B (W rows, hi/lo split) ----
    for (int q = tid; q < 64 * KQ; q += 512) {
        int r = q / KQ, c = (q % KQ) * 4;
        float4 v = *(const float4*)(W + (long)r * KD + c);
        float xs[4] = {v.x, v.y, v.z, v.w};
        float hs[4], ls[4];
#pragma unroll
        for (int j = 0; j < 4; j++) {
            __nv_bfloat16 h = __float2bfloat16(xs[j]);
            hs[j] = __bfloat162float(h);
            ls[j] = xs[j] - hs[j];
        }
        int w = r * PW + (c >> 1);
        Bh[w]     = pack_bf16(hs[0], hs[1]);
        Bh[w + 1] = pack_bf16(hs[2], hs[3]);
        Bl[w]     = pack_bf16(ls[0], ls[1]);
        Bl[w + 1] = pack_bf16(ls[2], ls[3]);
    }
    __syncthreads();

    const int warp = tid >> 5, lane = tid & 31;
    const int wrow = (warp & 7) * 16;     // row group (0..112)
    const int nt0 = (warp >> 3) * 4;      // n-tile base (4 tiles of n8)

    float acc[4][4];
#pragma unroll
    for (int nt = 0; nt < 4; nt++)
#pragma unroll
        for (int j = 0; j < 4; j++) acc[nt][j] = 0.f;

    // ---- LDSM addresses ----
    const uint32_t smbase = (uint32_t)__cvta_generic_to_shared(sm);
    const int mA = lane >> 3;
    const uint32_t aoffw = (uint32_t)((wrow + (lane & 7) + (mA & 1) * 8) * PW + (mA >> 1) * 4);
    const uint32_t aHaddr = smbase + aoffw * 4;
    const uint32_t aLaddr = aHaddr + T_A * 4;
    const int l15 = lane & 15;
    uint32_t bHaddr[4], bLaddr[4];
#pragma unroll
    for (int nt = 0; nt < 4; nt++) {
        uint32_t boffw = (uint32_t)(((nt0 + nt) * 8 + (l15 & 7)) * PW + (l15 >> 3) * 4);
        bHaddr[nt] = smbase + (2 * T_A + boffw) * 4;
        bLaddr[nt] = bHaddr[nt] + T_B * 4;
    }

#pragma unroll
    for (int ks = 0; ks < KD / 16; ks++) {
        const uint32_t kb = (uint32_t)ks * 32;   // 8 words per k16 step
        uint32_t ah[4], al[4];
        ldsm_x4(aHaddr + kb, ah);
        ldsm_x4(aLaddr + kb, al);
#pragma unroll
        for (int nt = 0; nt < 4; nt++) {
            uint32_t bh[2], bl[2];
            ldsm_x2(bHaddr[nt] + kb, bh);
            ldsm_x2(bLaddr[nt] + kb, bl);
            mma16816(acc[nt], ah, bh[0], bh[1]);
            mma16816(acc[nt], al, bh[0], bh[1]);
            mma16816(acc[nt], ah, bl[0], bl[1]);
        }
    }

    // ---- epilogue ----
    const int rA = lane >> 2;
    const int kq = lane & 3;
    const long r_lo = row0 + wrow + rA;
    const long r_hi = r_lo + 8;
#pragma unroll
    for (int nt = 0; nt < 4; nt++) {
        int col = (nt0 + nt) * 8 + kq * 2;
        float2 v0 = make_float2(acc[nt][0] + bsh[col], acc[nt][1] + bsh[col + 1]);
        float2 v1 = make_float2(acc[nt][2] + bsh[col], acc[nt][3] + bsh[col + 1]);
        if (do_relu) {
            v0.x = fmaxf(v0.x, 0.f); v0.y = fmaxf(v0.y, 0.f);
            v1.x = fmaxf(v1.x, 0.f); v1.y = fmaxf(v1.y, 0.f);
        }
        if (r_lo < NN) *(float2*)(out + r_lo * 64 + col) = v0;
        if (r_hi < NN) *(float2*)(out + r_hi * 64 + col) = v1;
    }
}

// ------------- normalized SpMM: Sout[n,:] = dinv[n] * sum_{e: dst=n} dinv[s]*Xin[s,:] -------------
// Warp per node, float2 per lane; 4-way unrolled gather for MLP.
__global__ void __launch_bounds__(256) spmm_norm_kernel(const float* __restrict__ Xin,
                                                        float* __restrict__ Sout) {
    int n = (blockIdx.x * 256 + threadIdx.x) >> 5;
    if (n >= NN) return;
    int lane = threadIdx.x & 31;
    int cnt = g_cnt[n];
    if (cnt > BCAP) cnt = BCAP;
    const int* bk = &g_bucket[(size_t)n * BCAP];
    const float* xb = Xin + (size_t)lane * 2;
    float2 a0 = make_float2(0.f, 0.f), a1 = make_float2(0.f, 0.f);
    float2 a2 = make_float2(0.f, 0.f), a3 = make_float2(0.f, 0.f);
    int i = 0;
    for (; i + 3 < cnt; i += 4) {
        int s0 = bk[i], s1 = bk[i + 1], s2 = bk[i + 2], s3 = bk[i + 3];
        float d0 = g_dinv[s0], d1 = g_dinv[s1], d2 = g_dinv[s2], d3 = g_dinv[s3];
        float2 v0 = *(const float2*)(xb + (size_t)s0 * 64);
        float2 v1 = *(const float2*)(xb + (size_t)s1 * 64);
        float2 v2 = *(const float2*)(xb + (size_t)s2 * 64);
        float2 v3 = *(const float2*)(xb + (size_t)s3 * 64);
        a0.x = fmaf(v0.x, d0, a0.x); a0.y = fmaf(v0.y, d0, a0.y);
        a1.x = fmaf(v1.x, d1, a1.x); a1.y = fmaf(v1.y, d1, a1.y);
        a2.x = fmaf(v2.x, d2, a2.x); a2.y = fmaf(v2.y, d2, a2.y);
        a3.x = fmaf(v3.x, d3, a3.x); a3.y = fmaf(v3.y, d3, a3.y);
    }
    for (; i < cnt; i++) {
        int s = bk[i];
        float ds = g_dinv[s];
        float2 v = *(const float2*)(xb + (size_t)s * 64);
        a0.x = fmaf(v.x, ds, a0.x); a0.y = fmaf(v.y, ds, a0.y);
    }
    float dn = g_dinv[n];
    float2 acc;
    acc.x = ((a0.x + a1.x) + (a2.x + a3.x)) * dn;
    acc.y = ((a0.y + a1.y) + (a2.y + a3.y)) * dn;
    *(float2*)(Sout + (size_t)n * 64 + lane * 2) = acc;
}

// ---------------- final head: out[N,2] = X[N,64] @ W4[2,64]^T + b4 ----------------
__global__ void __launch_bounds__(256) gemm_out_kernel(const float* __restrict__ X,
                                                       const float* __restrict__ W,
                                                       const float* __restrict__ b,
                                                       float* __restrict__ out) {
    __shared__ float Wsh[128];
    __shared__ float bsh[2];
    if (threadIdx.x < 128) Wsh[threadIdx.x] = W[threadIdx.x];
    if (threadIdx.x < 2)   bsh[threadIdx.x] = b[threadIdx.x];
    __syncthreads();
    int r = blockIdx.x * 256 + threadIdx.x;
    if (r >= NN) return;
    float a0 = bsh[0], a1 = bsh[1];
    const float* xr = X + (size_t)r * 64;
#pragma unroll
    for (int k = 0; k < 64; k += 4) {
        float4 xv = *(const float4*)(xr + k);
        a0 = fmaf(xv.x, Wsh[k], fmaf(xv.y, Wsh[k + 1], fmaf(xv.z, Wsh[k + 2], fmaf(xv.w, Wsh[k + 3], a0))));
        a1 = fmaf(xv.x, Wsh[64 + k], fmaf(xv.y, Wsh[64 + k + 1], fmaf(xv.z, Wsh[64 + k + 2], fmaf(xv.w, Wsh[64 + k + 3], a1))));
    }
    out[(size_t)r * 2 + 0] = a0;
    out[(size_t)r * 2 + 1] = a1;
}

// ---------------- launch ----------------
static inline int gemm_smem_bytes(int kd) { return 384 * (kd / 2 + 4) * 4; }

extern "C" void kernel_launch(void* const* d_in, const int* in_sizes, int n_in,
                              void* d_out, int out_size) {
    const float* in_feat = (const float*)d_in[0];
    const int*   src     = (const int*)d_in[1];
    const int*   dst     = (const int*)d_in[2];
    const float* W1  = (const float*)d_in[3];
    const float* b1  = (const float*)d_in[4];
    const float* W2  = (const float*)d_in[5];
    const float* b2  = (const float*)d_in[6];
    const float* Wc1 = (const float*)d_in[7];
    const float* bc1 = (const float*)d_in[8];
    const float* Wc2 = (const float*)d_in[9];
    const float* bc2 = (const float*)d_in[10];
    const float* W3  = (const float*)d_in[11];
    const float* b3  = (const float*)d_in[12];
    const float* W4  = (const float*)d_in[13];
    const float* b4  = (const float*)d_in[14];
    float* out = (float*)d_out;

    float *h1, *h2, *S1, *S2, *c1, *c2, *h3;
    cudaGetSymbolAddress((void**)&h1, g_h1);
    cudaGetSymbolAddress((void**)&h2, g_h2);
    cudaGetSymbolAddress((void**)&S1, g_S1);
    cudaGetSymbolAddress((void**)&S2, g_S2);
    cudaGetSymbolAddress((void**)&c1, g_c1);
    cudaGetSymbolAddress((void**)&c2, g_c2);
    cudaGetSymbolAddress((void**)&h3, g_h3);

    cudaFuncSetAttribute(gemm_mma_kernel<128,0>, cudaFuncAttributeMaxDynamicSharedMemorySize, gemm_smem_bytes(128));
    cudaFuncSetAttribute(gemm_mma_kernel<64,0>,  cudaFuncAttributeMaxDynamicSharedMemorySize, gemm_smem_bytes(64));
    cudaFuncSetAttribute(gemm_mma_kernel<192,1>, cudaFuncAttributeMaxDynamicSharedMemorySize, gemm_smem_bytes(192));

    const int GN  = (NN + 255) / 256;
    const int GE  = EE / 256;
    const int GT  = (NN + 127) / 128;      // 391 GEMM CTAs (128 rows each)
    const int GW  = (NN * 32 + 255) / 256; // warp-per-node spmm

    // graph structure
    zero_cnt_kernel<<<GN, 256>>>();
    build_bucket_kernel<<<GE, 256>>>(src, dst);
    dinv_kernel<<<GN, 256>>>();

    // MLP front
    gemm_mma_kernel<128,0><<<GT, 512, gemm_smem_bytes(128)>>>(in_feat, nullptr, nullptr, W1, b1, h1, 1);
    gemm_mma_kernel<64,0><<<GT, 512, gemm_smem_bytes(64)>>>(h1, nullptr, nullptr, W2, b2, h2, 1);

    // ChebConv 1: S1 = a_norm(h2), S2 = a_norm(S1), c1 = relu([h2|-S1|2S2-h2] @ Wc1^T + bc1)
    spmm_norm_kernel<<<GW, 256>>>(h2, S1);
    spmm_norm_kernel<<<GW, 256>>>(S1, S2);
    gemm_mma_kernel<192,1><<<GT, 512, gemm_smem_bytes(192)>>>(h2, S1, S2, Wc1, bc1, c1, 1);

    // ChebConv 2
    spmm_norm_kernel<<<GW, 256>>>(c1, S1);
    spmm_norm_kernel<<<GW, 256>>>(S1, S2);
    gemm_mma_kernel<192,1><<<GT, 512, gemm_smem_bytes(192)>>>(c1, S1, S2, Wc2, bc2, c2, 1);

    // MLP back + head
    gemm_mma_kernel<64,0><<<GT, 512, gemm_smem_bytes(64)>>>(c2, nullptr, nullptr, W3, b3, h3, 1);
    gemm_out_kernel<<<GN, 256>>>(h3, W4, b4, out);
}

// round 9
// speedup vs baseline: 7.1707x; 1.1334x over previous
#include <cuda_runtime.h>
#include <cuda_bf16.h>
#include <cstdint>

#define NN 50000
#define EE 800000
#define BCAP 128

// ---------------- scratch (static device globals; no allocation) ----------------
__device__ int   g_cnt[NN];
__device__ int   g_bucket[(size_t)NN * BCAP];
__device__ float g_dinv[NN];
__device__ float g_h2 [(size_t)NN * 64];
__device__ float g_S1 [(size_t)NN * 64];
__device__ float g_S2 [(size_t)NN * 64];
__device__ float g_c1 [(size_t)NN * 64];
__device__ float g_c2 [(size_t)NN * 64];

__device__ __forceinline__ uint32_t pack_bf16(float a, float b) {
    __nv_bfloat162 t = __floats2bfloat162_rn(a, b);
    return *reinterpret_cast<uint32_t*>(&t);
}

// split two floats into hi (bf16 pair) and lo (residual bf16 pair)
__device__ __forceinline__ void split2(float a, float b, uint32_t& hi, uint32_t& lo) {
    __nv_bfloat16 ah = __float2bfloat16(a), bh = __float2bfloat16(b);
    __nv_bfloat162 hv; hv.x = ah; hv.y = bh;
    hi = *reinterpret_cast<uint32_t*>(&hv);
    lo = pack_bf16(a - __bfloat162float(ah), b - __bfloat162float(bh));
}

// split a float4 and store hi/lo pairs at word index w
__device__ __forceinline__ void split4store(uint32_t* Hi, uint32_t* Lo, int w, float4 v) {
    uint32_t h0, l0, h1, l1;
    split2(v.x, v.y, h0, l0);
    split2(v.z, v.w, h1, l1);
    Hi[w] = h0; Hi[w + 1] = h1;
    Lo[w] = l0; Lo[w + 1] = l1;
}

// mma.sync m16n8k16 bf16 -> f32 (baseline PTX, sm_80+)
__device__ __forceinline__ void mma16816(float* c, const uint32_t* a, uint32_t b0, uint32_t b1) {
    asm volatile(
        "mma.sync.aligned.m16n8k16.row.col.f32.bf16.bf16.f32 "
        "{%0,%1,%2,%3}, {%4,%5,%6,%7}, {%8,%9}, {%0,%1,%2,%3};"
        : "+f"(c[0]), "+f"(c[1]), "+f"(c[2]), "+f"(c[3])
        : "r"(a[0]), "r"(a[1]), "r"(a[2]), "r"(a[3]), "r"(b0), "r"(b1));
}

__device__ __forceinline__ void ldsm_x4(uint32_t addr, uint32_t* r) {
    asm volatile("ldmatrix.sync.aligned.m8n8.x4.shared.b16 {%0,%1,%2,%3}, [%4];"
                 : "=r"(r[0]), "=r"(r[1]), "=r"(r[2]), "=r"(r[3]) : "r"(addr));
}
__device__ __forceinline__ void ldsm_x2(uint32_t addr, uint32_t* r) {
    asm volatile("ldmatrix.sync.aligned.m8n8.x2.shared.b16 {%0,%1}, [%2];"
                 : "=r"(r[0]), "=r"(r[1]) : "r"(addr));
}

// 3-term bf16 split mainloop over a staged tile pair.
// A tiles at word 0 (hi) / TA_w (lo); B tiles at baseB_w (hi) / +TB_w (lo).
// PW must satisfy (PW/4) odd for conflict-free LDSM.
template <int PW, int NK>
__device__ __forceinline__ void run_mainloop(uint32_t smbase, int TA_w, int TB_w,
                                             int baseB_w, int wrow, int nt0,
                                             int lane, float acc[4][4]) {
    const int mA = lane >> 3;
    const uint32_t aH = smbase + (((wrow + (lane & 7) + (mA & 1) * 8) * PW + (mA >> 1) * 4) << 2);
    const uint32_t aL = aH + (TA_w << 2);
    const int l15 = lane & 15;
    uint32_t bH[4], bL[4];
#pragma unroll
    for (int nt = 0; nt < 4; nt++) {
        bH[nt] = smbase + ((baseB_w + ((nt0 + nt) * 8 + (l15 & 7)) * PW + (l15 >> 3) * 4) << 2);
        bL[nt] = bH[nt] + (TB_w << 2);
    }
#pragma unroll
    for (int ks = 0; ks < NK; ks++) {
        const uint32_t kb = (uint32_t)ks * 32;
        uint32_t ah[4], al[4];
        ldsm_x4(aH + kb, ah);
        ldsm_x4(aL + kb, al);
#pragma unroll
        for (int nt = 0; nt < 4; nt++) {
            uint32_t bh[2], bl[2];
            ldsm_x2(bH[nt] + kb, bh);
            ldsm_x2(bL[nt] + kb, bl);
            mma16816(acc[nt], ah, bh[0], bh[1]);
            mma16816(acc[nt], al, bh[0], bh[1]);
            mma16816(acc[nt], ah, bl[0], bl[1]);
        }
    }
}

// ---------------- graph structure build ----------------
__global__ void zero_cnt_kernel() {
    int i = blockIdx.x * 256 + threadIdx.x;
    if (i < NN) g_cnt[i] = 0;
}

__global__ void build_bucket_kernel(const int* __restrict__ src,
                                    const int* __restrict__ dst) {
    int e = blockIdx.x * 256 + threadIdx.x;
    if (e >= EE) return;
    int d = dst[e];
    int p = atomicAdd(&g_cnt[d], 1);
    if (p < BCAP) g_bucket[(size_t)d * BCAP + p] = src[e];
}

__global__ void dinv_kernel() {
    int i = blockIdx.x * 256 + threadIdx.x;
    if (i >= NN) return;
    int c = g_cnt[i];
    float d = (float)(c > 0 ? c : 1);
    g_dinv[i] = rsqrtf(d);
}

// =========== K-chunked cat-GEMM: out = relu([h|-S1|2S2-h] @ W[64,192]^T + b) =========
// CTA = 128 rows x 64 cols, 512 threads; chunks of KC=96 restaged in place -> 80KB smem.
template <int KD, int KC, int CAT>
__global__ void __launch_bounds__(512) gemm_mma_kernel(const float* __restrict__ X,
                                                       const float* __restrict__ S1,
                                                       const float* __restrict__ S2,
                                                       const float* __restrict__ W,
                                                       const float* __restrict__ bias,
                                                       float* __restrict__ out,
                                                       int do_relu) {
    constexpr int PW = KC / 2 + 4;
    constexpr int TA = 128 * PW, TB = 64 * PW;
    constexpr int NCH = KD / KC, NK = KC / 16, KQ = KC / 4;
    extern __shared__ uint32_t sm[];
    __shared__ float bsh[64];

    const int tid = threadIdx.x;
    const long row0 = (long)blockIdx.x * 128;
    if (tid < 64) bsh[tid] = bias[tid];

    const int warp = tid >> 5, lane = tid & 31;
    const int wrow = (warp & 7) * 16;
    const int nt0 = (warp >> 3) * 4;
    const uint32_t smbase = (uint32_t)__cvta_generic_to_shared(sm);

    float acc[4][4];
#pragma unroll
    for (int nt = 0; nt < 4; nt++)
#pragma unroll
        for (int j = 0; j < 4; j++) acc[nt][j] = 0.f;

#pragma unroll
    for (int ch = 0; ch < NCH; ch++) {
        if (ch) __syncthreads();
        // stage A chunk
        for (int q = tid; q < 128 * KQ; q += 512) {
            int r = q / KQ, cl = (q % KQ) * 4, gc = ch * KC + cl;
            long gr = row0 + r; if (gr >= NN) gr = NN - 1;
            float4 v;
            if (CAT) {
                if (gc < 64) {
                    v = *(const float4*)(X + gr * 64 + gc);
                } else if (gc < 128) {
                    float4 s = *(const float4*)(S1 + gr * 64 + (gc - 64));
                    v = make_float4(-s.x, -s.y, -s.z, -s.w);
                } else {
                    float4 s = *(const float4*)(S2 + gr * 64 + (gc - 128));
                    float4 h = *(const float4*)(X + gr * 64 + (gc - 128));
                    v = make_float4(fmaf(2.f, s.x, -h.x), fmaf(2.f, s.y, -h.y),
                                    fmaf(2.f, s.z, -h.z), fmaf(2.f, s.w, -h.w));
                }
            } else {
                v = *(const float4*)(X + gr * KD + gc);
            }
            split4store(sm, sm + TA, r * PW + (cl >> 1), v);
        }
        // stage B chunk
        for (int q = tid; q < 64 * KQ; q += 512) {
            int r = q / KQ, cl = (q % KQ) * 4, gc = ch * KC + cl;
            float4 v = *(const float4*)(W + (long)r * KD + gc);
            split4store(sm + 2 * TA, sm + 2 * TA + TB, r * PW + (cl >> 1), v);
        }
        __syncthreads();
        run_mainloop<PW, NK>(smbase, TA, TB, 2 * TA, wrow, nt0, lane, acc);
    }

    // epilogue
    const int rA = lane >> 2, kq = lane & 3;
    const long r_lo = row0 + wrow + rA, r_hi = r_lo + 8;
#pragma unroll
    for (int nt = 0; nt < 4; nt++) {
        int col = (nt0 + nt) * 8 + kq * 2;
        float2 v0 = make_float2(acc[nt][0] + bsh[col], acc[nt][1] + bsh[col + 1]);
        float2 v1 = make_float2(acc[nt][2] + bsh[col], acc[nt][3] + bsh[col + 1]);
        if (do_relu) {
            v0.x = fmaxf(v0.x, 0.f); v0.y = fmaxf(v0.y, 0.f);
            v1.x = fmaxf(v1.x, 0.f); v1.y = fmaxf(v1.y, 0.f);
        }
        if (r_lo < NN) *(float2*)(out + r_lo * 64 + col) = v0;
        if (r_hi < NN) *(float2*)(out + r_hi * 64 + col) = v1;
    }
}

// =========== fused front MLP: h2 = relu(relu(X@W1^T+b1)@W2^T+b2) ===========
// Pass 1: KD=128 staged tiles (PW1=68). Pass 2: h1 fragments relu+split in regs,
// restaged into the (dead) A1 smem region as KD=64 tiles (PW2=36); W2 staged after.
__global__ void __launch_bounds__(512) mlp_front_kernel(const float* __restrict__ X,
                                                        const float* __restrict__ W1,
                                                        const float* __restrict__ b1,
                                                        const float* __restrict__ W2,
                                                        const float* __restrict__ b2,
                                                        float* __restrict__ out) {
    constexpr int PW1 = 68, TA1 = 128 * PW1, TB1 = 64 * PW1;
    constexpr int PW2 = 36, TA2 = 128 * PW2, TB2 = 64 * PW2;
    extern __shared__ uint32_t sm[];
    __shared__ float bsh1[64], bsh2[64];

    const int tid = threadIdx.x;
    const long row0 = (long)blockIdx.x * 128;
    if (tid < 64) { bsh1[tid] = b1[tid]; bsh2[tid] = b2[tid]; }

    // stage A1 (X, 128 cols)
    for (int q = tid; q < 128 * 32; q += 512) {
        int r = q >> 5, c = (q & 31) * 4;
        long gr = row0 + r; if (gr >= NN) gr = NN - 1;
        float4 v = *(const float4*)(X + gr * 128 + c);
        split4store(sm, sm + TA1, r * PW1 + (c >> 1), v);
    }
    // stage B1 (W1)
    for (int q = tid; q < 64 * 32; q += 512) {
        int r = q >> 5, c = (q & 31) * 4;
        float4 v = *(const float4*)(W1 + (long)r * 128 + c);
        split4store(sm + 2 * TA1, sm + 2 * TA1 + TB1, r * PW1 + (c >> 1), v);
    }
    __syncthreads();

    const int warp = tid >> 5, lane = tid & 31;
    const int wrow = (warp & 7) * 16;
    const int nt0 = (warp >> 3) * 4;
    const uint32_t smbase = (uint32_t)__cvta_generic_to_shared(sm);

    float acc[4][4];
#pragma unroll
    for (int nt = 0; nt < 4; nt++)
#pragma unroll
        for (int j = 0; j < 4; j++) acc[nt][j] = 0.f;
    run_mainloop<PW1, 8>(smbase, TA1, TB1, 2 * TA1, wrow, nt0, lane, acc);
    __syncthreads();   // all warps done reading A1/B1 before overlay

    // epilogue1: h1 = relu(acc + b1) -> hi/lo fragments into A2 region (overlay)
    {
        const int rA = lane >> 2, kq = lane & 3;
        const int rlo = wrow + rA, rhi = rlo + 8;
#pragma unroll
        for (int nt = 0; nt < 4; nt++) {
            int col = (nt0 + nt) * 8 + kq * 2;       // FIXED (was nt0*32 + ...)
            float v0x = fmaxf(acc[nt][0] + bsh1[col], 0.f);
            float v0y = fmaxf(acc[nt][1] + bsh1[col + 1], 0.f);
            float v1x = fmaxf(acc[nt][2] + bsh1[col], 0.f);
            float v1y = fmaxf(acc[nt][3] + bsh1[col + 1], 0.f);
            int w = col >> 1;
            uint32_t h0, l0, h1, l1;
            split2(v0x, v0y, h0, l0);
            split2(v1x, v1y, h1, l1);
            sm[rlo * PW2 + w]       = h0;
            sm[TA2 + rlo * PW2 + w] = l0;
            sm[rhi * PW2 + w]       = h1;
            sm[TA2 + rhi * PW2 + w] = l1;
        }
    }
    // stage B2 (W2, 64x64) after A2 region
    for (int q = tid; q < 64 * 16; q += 512) {
        int r = q >> 4, c = (q & 15) * 4;
        float4 v = *(const float4*)(W2 + (long)r * 64 + c);
        split4store(sm + 2 * TA2, sm + 2 * TA2 + TB2, r * PW2 + (c >> 1), v);
    }
    __syncthreads();

    float acc2[4][4];
#pragma unroll
    for (int nt = 0; nt < 4; nt++)
#pragma unroll
        for (int j = 0; j < 4; j++) acc2[nt][j] = 0.f;
    run_mainloop<PW2, 4>(smbase, TA2, TB2, 2 * TA2, wrow, nt0, lane, acc2);

    // epilogue2: h2 = relu(acc2 + b2) -> gmem
    const int rA = lane >> 2, kq = lane & 3;
    const long r_lo = row0 + wrow + rA, r_hi = r_lo + 8;
#pragma unroll
    for (int nt = 0; nt < 4; nt++) {
        int col = (nt0 + nt) * 8 + kq * 2;
        float2 v0 = make_float2(fmaxf(acc2[nt][0] + bsh2[col], 0.f),
                                fmaxf(acc2[nt][1] + bsh2[col + 1], 0.f));
        float2 v1 = make_float2(fmaxf(acc2[nt][2] + bsh2[col], 0.f),
                                fmaxf(acc2[nt][3] + bsh2[col + 1], 0.f));
        if (r_lo < NN) *(float2*)(out + r_lo * 64 + col) = v0;
        if (r_hi < NN) *(float2*)(out + r_hi * 64 + col) = v1;
    }
}

// =========== fused back MLP + head: out = relu(X@W3^T+b3) @ W4^T + b4 ===========
__global__ void __launch_bounds__(512) mlp_back_kernel(const float* __restrict__ X,
                                                       const float* __restrict__ W3,
                                                       const float* __restrict__ b3,
                                                       const float* __restrict__ W4,
                                                       const float* __restrict__ b4,
                                                       float* __restrict__ out) {
    constexpr int PW = 36, TA = 128 * PW, TB = 64 * PW;
    extern __shared__ uint32_t sm[];
    __shared__ float bsh[64], W4sh[128], b4sh[2];
    __shared__ float hp[2][128][2];

    const int tid = threadIdx.x;
    const long row0 = (long)blockIdx.x * 128;
    if (tid < 64)  bsh[tid] = b3[tid];
    if (tid < 128) W4sh[tid] = W4[tid];
    if (tid < 2)   b4sh[tid] = b4[tid];

    for (int q = tid; q < 128 * 16; q += 512) {
        int r = q >> 4, c = (q & 15) * 4;
        long gr = row0 + r; if (gr >= NN) gr = NN - 1;
        float4 v = *(const float4*)(X + gr * 64 + c);
        split4store(sm, sm + TA, r * PW + (c >> 1), v);
    }
    for (int q = tid; q < 64 * 16; q += 512) {
        int r = q >> 4, c = (q & 15) * 4;
        float4 v = *(const float4*)(W3 + (long)r * 64 + c);
        split4store(sm + 2 * TA, sm + 2 * TA + TB, r * PW + (c >> 1), v);
    }
    __syncthreads();

    const int warp = tid >> 5, lane = tid & 31;
    const int wrow = (warp & 7) * 16;
    const int nt0w = warp >> 3;            // 0 or 1 (n-half)
    const int nt0 = nt0w * 4;
    const uint32_t smbase = (uint32_t)__cvta_generic_to_shared(sm);

    float acc[4][4];
#pragma unroll
    for (int nt = 0; nt < 4; nt++)
#pragma unroll
        for (int j = 0; j < 4; j++) acc[nt][j] = 0.f;
    run_mainloop<PW, 4>(smbase, TA, TB, 2 * TA, wrow, nt0, lane, acc);

    // head: h3 = relu(acc + b3); partial dots with W4 rows
    const int rA = lane >> 2, kq = lane & 3;
    float p00 = 0.f, p01 = 0.f, p10 = 0.f, p11 = 0.f;
#pragma unroll
    for (int nt = 0; nt < 4; nt++) {
        int c = (nt0 + nt) * 8 + kq * 2;
        float v0x = fmaxf(acc[nt][0] + bsh[c], 0.f);
        float v0y = fmaxf(acc[nt][1] + bsh[c + 1], 0.f);
        float v1x = fmaxf(acc[nt][2] + bsh[c], 0.f);
        float v1y = fmaxf(acc[nt][3] + bsh[c + 1], 0.f);
        float w0a = W4sh[c], w0b = W4sh[c + 1];
        float w1a = W4sh[64 + c], w1b = W4sh[64 + c + 1];
        p00 = fmaf(v0x, w0a, fmaf(v0y, w0b, p00));
        p01 = fmaf(v0x, w1a, fmaf(v0y, w1b, p01));
        p10 = fmaf(v1x, w0a, fmaf(v1y, w0b, p10));
        p11 = fmaf(v1x, w1a, fmaf(v1y, w1b, p11));
    }
    p00 += __shfl_xor_sync(0xffffffffu, p00, 1); p00 += __shfl_xor_sync(0xffffffffu, p00, 2);
    p01 += __shfl_xor_sync(0xffffffffu, p01, 1); p01 += __shfl_xor_sync(0xffffffffu, p01, 2);
    p10 += __shfl_xor_sync(0xffffffffu, p10, 1); p10 += __shfl_xor_sync(0xffffffffu, p10, 2);
    p11 += __shfl_xor_sync(0xffffffffu, p11, 1); p11 += __shfl_xor_sync(0xffffffffu, p11, 2);
    if (kq == 0) {
        hp[nt0w][wrow + rA][0] = p00;
        hp[nt0w][wrow + rA][1] = p01;
        hp[nt0w][wrow + rA + 8][0] = p10;
        hp[nt0w][wrow + rA + 8][1] = p11;
    }
    __syncthreads();
    if (tid < 256) {
        int row = tid >> 1, cls = tid & 1;
        long gr = row0 + row;
        if (gr < NN) out[gr * 2 + cls] = hp[0][row][cls] + hp[1][row][cls] + b4sh[cls];
    }
}

// ------------- normalized SpMM: Sout[n,:] = dinv[n] * sum_{e: dst=n} dinv[s]*Xin[s,:] -------------
__global__ void __launch_bounds__(256) spmm_norm_kernel(const float* __restrict__ Xin,
                                                        float* __restrict__ Sout) {
    int n = (blockIdx.x * 256 + threadIdx.x) >> 5;
    if (n >= NN) return;
    int lane = threadIdx.x & 31;
    int cnt = g_cnt[n];
    if (cnt > BCAP) cnt = BCAP;
    const int* bk = &g_bucket[(size_t)n * BCAP];
    const float* xb = Xin + (size_t)lane * 2;
    float2 a0 = make_float2(0.f, 0.f), a1 = make_float2(0.f, 0.f);
    float2 a2 = make_float2(0.f, 0.f), a3 = make_float2(0.f, 0.f);
    int i = 0;
    for (; i + 3 < cnt; i += 4) {
        int s0 = bk[i], s1 = bk[i + 1], s2 = bk[i + 2], s3 = bk[i + 3];
        float d0 = g_dinv[s0], d1 = g_dinv[s1], d2 = g_dinv[s2], d3 = g_dinv[s3];
        float2 v0 = *(const float2*)(xb + (size_t)s0 * 64);
        float2 v1 = *(const float2*)(xb + (size_t)s1 * 64);
        float2 v2 = *(const float2*)(xb + (size_t)s2 * 64);
        float2 v3 = *(const float2*)(xb + (size_t)s3 * 64);
        a0.x = fmaf(v0.x, d0, a0.x); a0.y = fmaf(v0.y, d0, a0.y);
        a1.x = fmaf(v1.x, d1, a1.x); a1.y = fmaf(v1.y, d1, a1.y);
        a2.x = fmaf(v2.x, d2, a2.x); a2.y = fmaf(v2.y, d2, a2.y);
        a3.x = fmaf(v3.x, d3, a3.x); a3.y = fmaf(v3.y, d3, a3.y);
    }
    for (; i < cnt; i++) {
        int s = bk[i];
        float ds = g_dinv[s];
        float2 v = *(const float2*)(xb + (size_t)s * 64);
        a0.x = fmaf(v.x, ds, a0.x); a0.y = fmaf(v.y, ds, a0.y);
    }
    float dn = g_dinv[n];
    float2 acc;
    acc.x = ((a0.x + a1.x) + (a2.x + a3.x)) * dn;
    acc.y = ((a0.y + a1.y) + (a2.y + a3.y)) * dn;
    *(float2*)(Sout + (size_t)n * 64 + lane * 2) = acc;
}

// ---------------- launch ----------------
extern "C" void kernel_launch(void* const* d_in, const int* in_sizes, int n_in,
                              void* d_out, int out_size) {
    const float* in_feat = (const float*)d_in[0];
    const int*   src     = (const int*)d_in[1];
    const int*   dst     = (const int*)d_in[2];
    const float* W1  = (const float*)d_in[3];
    const float* b1  = (const float*)d_in[4];
    const float* W2  = (const float*)d_in[5];
    const float* b2  = (const float*)d_in[6];
    const float* Wc1 = (const float*)d_in[7];
    const float* bc1 = (const float*)d_in[8];
    const float* Wc2 = (const float*)d_in[9];
    const float* bc2 = (const float*)d_in[10];
    const float* W3  = (const float*)d_in[11];
    const float* b3  = (const float*)d_in[12];
    const float* W4  = (const float*)d_in[13];
    const float* b4  = (const float*)d_in[14];
    float* out = (float*)d_out;

    float *h2, *S1, *S2, *c1, *c2;
    cudaGetSymbolAddress((void**)&h2, g_h2);
    cudaGetSymbolAddress((void**)&S1, g_S1);
    cudaGetSymbolAddress((void**)&S2, g_S2);
    cudaGetSymbolAddress((void**)&c1, g_c1);
    cudaGetSymbolAddress((void**)&c2, g_c2);

    const int FRONT_SMEM = (2 * 128 * 68 + 2 * 64 * 68) * 4;   // 104448
    const int BACK_SMEM  = (2 * 128 * 36 + 2 * 64 * 36) * 4;   // 55296
    const int CAT_SMEM   = (2 * 128 * 52 + 2 * 64 * 52) * 4;   // 79872

    cudaFuncSetAttribute(mlp_front_kernel, cudaFuncAttributeMaxDynamicSharedMemorySize, FRONT_SMEM);
    cudaFuncSetAttribute(mlp_back_kernel,  cudaFuncAttributeMaxDynamicSharedMemorySize, BACK_SMEM);
    cudaFuncSetAttribute(gemm_mma_kernel<192, 96, 1>, cudaFuncAttributeMaxDynamicSharedMemorySize, CAT_SMEM);

    const int GN = (NN + 255) / 256;
    const int GE = EE / 256;
    const int GT = (NN + 127) / 128;       // 391 CTAs
    const int GW = (NN * 32 + 255) / 256;  // warp-per-node spmm

    // graph structure
    zero_cnt_kernel<<<GN, 256>>>();
    build_bucket_kernel<<<GE, 256>>>(src, dst);
    dinv_kernel<<<GN, 256>>>();

    // fused front MLP
    mlp_front_kernel<<<GT, 512, FRONT_SMEM>>>(in_feat, W1, b1, W2, b2, h2);

    // ChebConv 1
    spmm_norm_kernel<<<GW, 256>>>(h2, S1);
    spmm_norm_kernel<<<GW, 256>>>(S1, S2);
    gemm_mma_kernel<192, 96, 1><<<GT, 512, CAT_SMEM>>>(h2, S1, S2, Wc1, bc1, c1, 1);

    // ChebConv 2
    spmm_norm_kernel<<<GW, 256>>>(c1, S1);
    spmm_norm_kernel<<<GW, 256>>>(S1, S2);
    gemm_mma_kernel<192, 96, 1><<<GT, 512, CAT_SMEM>>>(c1, S1, S2, Wc2, bc2, c2, 1);

    // fused back MLP + head
    mlp_back_kernel<<<GT, 512, BACK_SMEM>>>(c2, W3, b3, W4, b4, out);
}